// round 2
// baseline (speedup 1.0000x reference)
#include <cuda_runtime.h>
#include <cstddef>

#define B_ 4
#define L_ 2048
#define E_ 512
#define H_ 8
#define DK_ 64
#define DV_ 64
#define NEG_ (-1e9f)

// ---- scratch (device globals; no allocations allowed) ----
__device__ float g_qh[B_ * L_ * H_ * DK_];   // [B,L,H,DK] == [8192,512]
__device__ float g_kh[B_ * L_ * H_ * DK_];
__device__ float g_vh[B_ * L_ * H_ * DV_];
__device__ float g_ctx[B_ * L_ * H_ * DV_];  // attn @ V, [B,L,H*DV]
__device__ float g_fc[B_ * L_ * E_];         // FC output before residual+LN

// ============================================================================
// Generic tiled GEMM:  C(MxN) = A(MxK) @ B^T  (+ bias), B stored [N,K]
// 64x64 tile, BK=16, 256 threads, 4x4 per thread. All dims divide evenly.
// ============================================================================
__global__ void gemm_nt_kernel(const float* __restrict__ A, int lda,
                               const float* __restrict__ Bm, int ldb,
                               float* __restrict__ C, int ldc,
                               int K, const float* __restrict__ bias)
{
    __shared__ float As[16][65];
    __shared__ float Bs[16][65];
    int tid = threadIdx.x;
    int tx = tid & 15, ty = tid >> 4;
    int row0 = blockIdx.y * 64, col0 = blockIdx.x * 64;
    float acc[4][4] = {};

    for (int k0 = 0; k0 < K; k0 += 16) {
#pragma unroll
        for (int i = 0; i < 4; i++) {
            int idx = tid + i * 256;
            int kk = idx & 15, m = idx >> 4;
            As[kk][m] = A[(size_t)(row0 + m) * lda + k0 + kk];
            Bs[kk][m] = Bm[(size_t)(col0 + m) * ldb + k0 + kk];
        }
        __syncthreads();
#pragma unroll
        for (int kk = 0; kk < 16; kk++) {
            float a[4], b[4];
#pragma unroll
            for (int i = 0; i < 4; i++) a[i] = As[kk][ty * 4 + i];
#pragma unroll
            for (int j = 0; j < 4; j++) b[j] = Bs[kk][tx * 4 + j];
#pragma unroll
            for (int i = 0; i < 4; i++)
#pragma unroll
                for (int j = 0; j < 4; j++) acc[i][j] += a[i] * b[j];
        }
        __syncthreads();
    }
#pragma unroll
    for (int i = 0; i < 4; i++) {
        int r = row0 + ty * 4 + i;
#pragma unroll
        for (int j = 0; j < 4; j++) {
            int c = col0 + tx * 4 + j;
            float v = acc[i][j];
            if (bias) v += bias[c];
            C[(size_t)r * ldc + c] = v;
        }
    }
}

// ============================================================================
// Scores: attn[z, q, k] = (qh . kh)/8, masked with -1e9.  z = h*B + b
// qh/kh: [B,L,H,DK] -> for fixed (b,h): base (b*L*H + h)*DK, row stride 512
// Mask dtype is auto-detected (int32 vs uint8): if the buffer holds int32
// 0/1 values, every u32 word <= 1; packed random 0/1 bytes make words > 1.
// ============================================================================
__global__ void scores_kernel(const float* __restrict__ qh,
                              const float* __restrict__ kh,
                              const void* __restrict__ mask,
                              float* __restrict__ attn)
{
    int z = blockIdx.z;
    int h = z / B_, b = z % B_;
    const float* A  = qh + (size_t)(b * L_ * H_ + h) * DK_;
    const float* Bm = kh + (size_t)(b * L_ * H_ + h) * DK_;
    float* C = attn + (size_t)z * L_ * L_;

    __shared__ float As[16][65];
    __shared__ float Bs[16][65];
    __shared__ int s_byte_mode;
    int tid = threadIdx.x;
    int tx = tid & 15, ty = tid >> 4;
    int row0 = blockIdx.y * 64, col0 = blockIdx.x * 64;
    float acc[4][4] = {};

    if (tid == 0) {
        const unsigned int* mi = (const unsigned int*)mask;
        int bm = 0;
        for (int i = 0; i < 256; i++) if (mi[i] > 1u) bm = 1;
        s_byte_mode = bm;
    }

    for (int k0 = 0; k0 < DK_; k0 += 16) {
#pragma unroll
        for (int i = 0; i < 4; i++) {
            int idx = tid + i * 256;
            int kk = idx & 15, m = idx >> 4;
            As[kk][m] = A[(size_t)(row0 + m) * (H_ * DK_) + k0 + kk];
            Bs[kk][m] = Bm[(size_t)(col0 + m) * (H_ * DK_) + k0 + kk];
        }
        __syncthreads();
#pragma unroll
        for (int kk = 0; kk < 16; kk++) {
            float a[4], bb[4];
#pragma unroll
            for (int i = 0; i < 4; i++) a[i] = As[kk][ty * 4 + i];
#pragma unroll
            for (int j = 0; j < 4; j++) bb[j] = Bs[kk][tx * 4 + j];
#pragma unroll
            for (int i = 0; i < 4; i++)
#pragma unroll
                for (int j = 0; j < 4; j++) acc[i][j] += a[i] * bb[j];
        }
        __syncthreads();
    }

    int byte_mode = s_byte_mode;
    const size_t mbase = (size_t)b * L_ * L_;
#pragma unroll
    for (int i = 0; i < 4; i++) {
        int r = row0 + ty * 4 + i;
#pragma unroll
        for (int j = 0; j < 4; j++) {
            int c = col0 + tx * 4 + j;
            float v = acc[i][j] * 0.125f;            // / sqrt(64)
            size_t midx = mbase + (size_t)r * L_ + c;
            bool masked = byte_mode
                ? (((const unsigned char*)mask)[midx] != 0)
                : (((const int*)mask)[midx] != 0);
            if (masked) v = NEG_;
            C[(size_t)r * L_ + c] = v;
        }
    }
}

// ============================================================================
// Row softmax in place. One block per row of 2048, 256 threads x 8 elems.
// ============================================================================
__global__ void softmax_kernel(float* __restrict__ attn)
{
    float* p = attn + (size_t)blockIdx.x * L_;
    int tid = threadIdx.x;
    float v[8];
    float m = -3.4e38f;
#pragma unroll
    for (int i = 0; i < 8; i++) { v[i] = p[tid + i * 256]; m = fmaxf(m, v[i]); }

    __shared__ float red[8];
#pragma unroll
    for (int o = 16; o; o >>= 1) m = fmaxf(m, __shfl_xor_sync(0xffffffffu, m, o));
    if ((tid & 31) == 0) red[tid >> 5] = m;
    __syncthreads();
    m = red[0];
#pragma unroll
    for (int i = 1; i < 8; i++) m = fmaxf(m, red[i]);

    float s = 0.f;
#pragma unroll
    for (int i = 0; i < 8; i++) { v[i] = __expf(v[i] - m); s += v[i]; }
#pragma unroll
    for (int o = 16; o; o >>= 1) s += __shfl_xor_sync(0xffffffffu, s, o);
    __syncthreads();                      // red reuse
    if ((tid & 31) == 0) red[tid >> 5] = s;
    __syncthreads();
    s = 0.f;
#pragma unroll
    for (int i = 0; i < 8; i++) s += red[i];

    float inv = 1.0f / s;
#pragma unroll
    for (int i = 0; i < 8; i++) p[tid + i * 256] = v[i] * inv;
}

// ============================================================================
// ctx[b,q,h,:] = attn[z] (2048x2048) @ vh[b,:,h,:] (2048x64)   (NN GEMM)
// ============================================================================
__global__ void av_kernel(const float* __restrict__ attn,
                          const float* __restrict__ vh,
                          float* __restrict__ ctx)
{
    int z = blockIdx.z;
    int h = z / B_, b = z % B_;
    const float* A  = attn + (size_t)z * L_ * L_;
    const float* Bv = vh + (size_t)(b * L_ * H_ + h) * DV_;
    float* C = ctx + (size_t)(b * L_ * H_ + h) * DV_;

    __shared__ float As[16][65];
    __shared__ float Bs[16][65];
    int tid = threadIdx.x;
    int tx = tid & 15, ty = tid >> 4;
    int row0 = blockIdx.y * 64;           // col0 = 0 (N = 64)
    float acc[4][4] = {};

    for (int k0 = 0; k0 < L_; k0 += 16) {
#pragma unroll
        for (int i = 0; i < 4; i++) {
            int idx = tid + i * 256;
            int kk = idx & 15, m = idx >> 4;
            As[kk][m] = A[(size_t)(row0 + m) * L_ + k0 + kk];
        }
#pragma unroll
        for (int i = 0; i < 4; i++) {
            int idx = tid + i * 256;
            int n = idx & 63, kk = idx >> 6;
            Bs[kk][n] = Bv[(size_t)(k0 + kk) * (H_ * DV_) + n];
        }
        __syncthreads();
#pragma unroll
        for (int kk = 0; kk < 16; kk++) {
            float a[4], bb[4];
#pragma unroll
            for (int i = 0; i < 4; i++) a[i] = As[kk][ty * 4 + i];
#pragma unroll
            for (int j = 0; j < 4; j++) bb[j] = Bs[kk][tx * 4 + j];
#pragma unroll
            for (int i = 0; i < 4; i++)
#pragma unroll
                for (int j = 0; j < 4; j++) acc[i][j] += a[i] * bb[j];
        }
        __syncthreads();
    }
#pragma unroll
    for (int i = 0; i < 4; i++) {
        int r = row0 + ty * 4 + i;
#pragma unroll
        for (int j = 0; j < 4; j++) {
            int c = tx * 4 + j;
            C[(size_t)r * (H_ * DV_) + c] = acc[i][j];
        }
    }
}

// ============================================================================
// Residual add + LayerNorm. One block per row of 512, 256 threads x 2 elems.
// ============================================================================
__global__ void ln_kernel(const float* __restrict__ fc,
                          const float* __restrict__ resid,
                          const float* __restrict__ gamma,
                          const float* __restrict__ beta,
                          float* __restrict__ out)
{
    size_t base = (size_t)blockIdx.x * E_;
    int tid = threadIdx.x;
    float x0 = fc[base + tid] + resid[base + tid];
    float x1 = fc[base + tid + 256] + resid[base + tid + 256];
    float s = x0 + x1;
    float ss = x0 * x0 + x1 * x1;

    __shared__ float rs[8], rss[8];
#pragma unroll
    for (int o = 16; o; o >>= 1) {
        s  += __shfl_xor_sync(0xffffffffu, s, o);
        ss += __shfl_xor_sync(0xffffffffu, ss, o);
    }
    if ((tid & 31) == 0) { rs[tid >> 5] = s; rss[tid >> 5] = ss; }
    __syncthreads();
    s = 0.f; ss = 0.f;
#pragma unroll
    for (int i = 0; i < 8; i++) { s += rs[i]; ss += rss[i]; }

    float mu = s * (1.0f / E_);
    float var = ss * (1.0f / E_) - mu * mu;
    float rstd = rsqrtf(var + 1e-5f);
    out[base + tid]       = (x0 - mu) * rstd * gamma[tid] + beta[tid];
    out[base + tid + 256] = (x1 - mu) * rstd * gamma[tid + 256] + beta[tid + 256];
}

// ============================================================================
extern "C" void kernel_launch(void* const* d_in, const int* in_sizes, int n_in,
                              void* d_out, int out_size)
{
    const float* q    = (const float*)d_in[0];
    const float* k    = (const float*)d_in[1];
    const float* v    = (const float*)d_in[2];
    const void*  mask = (const void*)d_in[3];
    const float* Wq   = (const float*)d_in[4];
    const float* bq   = (const float*)d_in[5];
    const float* Wk   = (const float*)d_in[6];
    const float* bk   = (const float*)d_in[7];
    const float* Wv   = (const float*)d_in[8];
    const float* bv   = (const float*)d_in[9];
    const float* Wfc  = (const float*)d_in[10];
    const float* bfc  = (const float*)d_in[11];
    const float* gamma = (const float*)d_in[12];
    const float* beta  = (const float*)d_in[13];

    float* out  = (float*)d_out;                      // [B,L,E]
    float* attn = out + (size_t)B_ * L_ * E_;          // [H*B, L, L]

    float *qh, *kh, *vh, *ctx, *fc;
    cudaGetSymbolAddress((void**)&qh,  g_qh);
    cudaGetSymbolAddress((void**)&kh,  g_kh);
    cudaGetSymbolAddress((void**)&vh,  g_vh);
    cudaGetSymbolAddress((void**)&ctx, g_ctx);
    cudaGetSymbolAddress((void**)&fc,  g_fc);

    dim3 blk(256);

    // QKV projections: [8192,512] = [8192,512] @ W^T + b
    dim3 gproj((H_ * DK_) / 64, (B_ * L_) / 64);       // (8, 128)
    gemm_nt_kernel<<<gproj, blk>>>(q, E_, Wq, E_, qh, H_ * DK_, E_, bq);
    gemm_nt_kernel<<<gproj, blk>>>(k, E_, Wk, E_, kh, H_ * DK_, E_, bk);
    gemm_nt_kernel<<<gproj, blk>>>(v, E_, Wv, E_, vh, H_ * DV_, E_, bv);

    // scores + mask -> attns region of d_out
    dim3 gsc(L_ / 64, L_ / 64, H_ * B_);               // (32, 32, 32)
    scores_kernel<<<gsc, blk>>>(qh, kh, mask, attn);

    // row softmax in place
    softmax_kernel<<<H_ * B_ * L_, 256>>>(attn);

    // attn @ V
    dim3 gav(1, L_ / 64, H_ * B_);                     // (1, 32, 32)
    av_kernel<<<gav, blk>>>(attn, vh, ctx);

    // FC
    dim3 gfc(E_ / 64, (B_ * L_) / 64);
    gemm_nt_kernel<<<gfc, blk>>>(ctx, H_ * DV_, Wfc, H_ * DV_, fc, E_, H_ * DV_, bfc);

    // residual + LayerNorm -> outputs region of d_out
    ln_kernel<<<B_ * L_, 256>>>(fc, q, gamma, beta, out);
}

// round 3
// speedup vs baseline: 1.6096x; 1.6096x over previous
#include <cuda_runtime.h>
#include <cstddef>

#define B_ 4
#define L_ 2048
#define E_ 512
#define H_ 8
#define DK_ 64
#define DV_ 64
#define NEG_ (-1e9f)

// ---- scratch (device globals; no allocations allowed) ----
__device__ float g_qh[B_ * L_ * H_ * DK_];   // [B,L,H,DK] == [8192,512]
__device__ float g_kh[B_ * L_ * H_ * DK_];
__device__ float g_vh[B_ * L_ * H_ * DV_];
__device__ float g_ctx[B_ * L_ * H_ * DV_];  // attn @ V, [B,L,H*DV]
__device__ float g_fc[B_ * L_ * E_];         // FC output before residual+LN

// ============================================================================
// 128x128 GEMM body: C = A @ B^T + bias.  A[M,K] lda, Bw[N,K] ldb.
// 256 threads, 8x8 per thread (split as 2x2 groups of 4x4 for conflict-free
// float4 smem reads), BK=16.
// ============================================================================
__device__ __forceinline__ void gemm128_body(
    const float* __restrict__ A, int lda,
    const float* __restrict__ Bw, int ldb,
    float* __restrict__ C, int ldc,
    int K, const float* __restrict__ bias,
    int row0, int col0,
    float (&As)[16][132], float (&Bs)[16][132])
{
    int tid = threadIdx.x;
    int tx = tid & 15, ty = tid >> 4;
    int lr = tid >> 1;            // 0..127
    int lk = (tid & 1) * 8;       // 0 or 8
    float acc[8][8];
#pragma unroll
    for (int i = 0; i < 8; i++)
#pragma unroll
        for (int j = 0; j < 8; j++) acc[i][j] = 0.f;

    const float* Ap = A + (size_t)(row0 + lr) * lda + lk;
    const float* Bp = Bw + (size_t)(col0 + lr) * ldb + lk;

    for (int k0 = 0; k0 < K; k0 += 16) {
        float4 a0 = *(const float4*)(Ap + k0);
        float4 a1 = *(const float4*)(Ap + k0 + 4);
        float4 b0 = *(const float4*)(Bp + k0);
        float4 b1 = *(const float4*)(Bp + k0 + 4);
        As[lk + 0][lr] = a0.x; As[lk + 1][lr] = a0.y;
        As[lk + 2][lr] = a0.z; As[lk + 3][lr] = a0.w;
        As[lk + 4][lr] = a1.x; As[lk + 5][lr] = a1.y;
        As[lk + 6][lr] = a1.z; As[lk + 7][lr] = a1.w;
        Bs[lk + 0][lr] = b0.x; Bs[lk + 1][lr] = b0.y;
        Bs[lk + 2][lr] = b0.z; Bs[lk + 3][lr] = b0.w;
        Bs[lk + 4][lr] = b1.x; Bs[lk + 5][lr] = b1.y;
        Bs[lk + 6][lr] = b1.z; Bs[lk + 7][lr] = b1.w;
        __syncthreads();
#pragma unroll
        for (int kk = 0; kk < 16; kk++) {
            float a[8], b[8];
            *(float4*)&a[0] = *(const float4*)&As[kk][ty * 4];
            *(float4*)&a[4] = *(const float4*)&As[kk][64 + ty * 4];
            *(float4*)&b[0] = *(const float4*)&Bs[kk][tx * 4];
            *(float4*)&b[4] = *(const float4*)&Bs[kk][64 + tx * 4];
#pragma unroll
            for (int i = 0; i < 8; i++)
#pragma unroll
                for (int j = 0; j < 8; j++) acc[i][j] += a[i] * b[j];
        }
        __syncthreads();
    }

#pragma unroll
    for (int ih = 0; ih < 2; ih++)
#pragma unroll
        for (int i = 0; i < 4; i++) {
            int r = row0 + ih * 64 + ty * 4 + i;
#pragma unroll
            for (int jh = 0; jh < 2; jh++) {
                int c = col0 + jh * 64 + tx * 4;
                float4 bb = *(const float4*)&bias[c];
                float4 o;
                o.x = acc[ih * 4 + i][jh * 4 + 0] + bb.x;
                o.y = acc[ih * 4 + i][jh * 4 + 1] + bb.y;
                o.z = acc[ih * 4 + i][jh * 4 + 2] + bb.z;
                o.w = acc[ih * 4 + i][jh * 4 + 3] + bb.w;
                *(float4*)&C[(size_t)r * ldc + c] = o;
            }
        }
}

// Fused QKV projection: z selects which of the three GEMMs.
__global__ __launch_bounds__(256, 2) void qkv_kernel(
    const float* __restrict__ q, const float* __restrict__ k,
    const float* __restrict__ v,
    const float* __restrict__ Wq, const float* __restrict__ bq,
    const float* __restrict__ Wk, const float* __restrict__ bk,
    const float* __restrict__ Wv, const float* __restrict__ bv,
    float* __restrict__ qh, float* __restrict__ kh, float* __restrict__ vh)
{
    __shared__ float As[16][132];
    __shared__ float Bs[16][132];
    const float* A; const float* W; const float* bias; float* C;
    if (blockIdx.z == 0)      { A = q; W = Wq; bias = bq; C = qh; }
    else if (blockIdx.z == 1) { A = k; W = Wk; bias = bk; C = kh; }
    else                      { A = v; W = Wv; bias = bv; C = vh; }
    gemm128_body(A, E_, W, E_, C, H_ * DK_, E_, bias,
                 blockIdx.y * 128, blockIdx.x * 128, As, Bs);
}

__global__ __launch_bounds__(256, 2) void fc_kernel(
    const float* __restrict__ ctx, const float* __restrict__ Wfc,
    const float* __restrict__ bfc, float* __restrict__ fc)
{
    __shared__ float As[16][132];
    __shared__ float Bs[16][132];
    gemm128_body(ctx, H_ * DV_, Wfc, H_ * DV_, fc, E_, H_ * DV_, bfc,
                 blockIdx.y * 128, blockIdx.x * 128, As, Bs);
}

// ============================================================================
// Scores: attn[z,q,k] = (qh.kh)/8, masked with -1e9.  z = h*B+b.
// 128x128 tile version with vectorized mask epilogue.
// Mask dtype auto-detect (int32 vs uint8) via word scan.
// ============================================================================
__global__ __launch_bounds__(256, 2) void scores_kernel(
    const float* __restrict__ qh, const float* __restrict__ kh,
    const void* __restrict__ mask, float* __restrict__ attn)
{
    int z = blockIdx.z;
    int h = z / B_, b = z % B_;
    const float* A  = qh + (size_t)(b * L_ * H_ + h) * DK_;
    const float* Bm = kh + (size_t)(b * L_ * H_ + h) * DK_;
    float* C = attn + (size_t)z * L_ * L_;

    __shared__ float As[16][132];
    __shared__ float Bs[16][132];
    __shared__ int s_byte_mode;
    int tid = threadIdx.x;
    int tx = tid & 15, ty = tid >> 4;
    int row0 = blockIdx.y * 128, col0 = blockIdx.x * 128;
    int lr = tid >> 1;
    int lk = (tid & 1) * 8;

    if (tid == 0) {
        const unsigned int* mi = (const unsigned int*)mask;
        int bm = 0;
#pragma unroll 8
        for (int i = 0; i < 64; i++) if (mi[i] > 1u) bm = 1;
        s_byte_mode = bm;
    }

    float acc[8][8];
#pragma unroll
    for (int i = 0; i < 8; i++)
#pragma unroll
        for (int j = 0; j < 8; j++) acc[i][j] = 0.f;

    const float* Ap = A + (size_t)(row0 + lr) * (H_ * DK_) + lk;
    const float* Bp = Bm + (size_t)(col0 + lr) * (H_ * DK_) + lk;

    for (int k0 = 0; k0 < DK_; k0 += 16) {
        float4 a0 = *(const float4*)(Ap + k0);
        float4 a1 = *(const float4*)(Ap + k0 + 4);
        float4 b0 = *(const float4*)(Bp + k0);
        float4 b1 = *(const float4*)(Bp + k0 + 4);
        As[lk + 0][lr] = a0.x; As[lk + 1][lr] = a0.y;
        As[lk + 2][lr] = a0.z; As[lk + 3][lr] = a0.w;
        As[lk + 4][lr] = a1.x; As[lk + 5][lr] = a1.y;
        As[lk + 6][lr] = a1.z; As[lk + 7][lr] = a1.w;
        Bs[lk + 0][lr] = b0.x; Bs[lk + 1][lr] = b0.y;
        Bs[lk + 2][lr] = b0.z; Bs[lk + 3][lr] = b0.w;
        Bs[lk + 4][lr] = b1.x; Bs[lk + 5][lr] = b1.y;
        Bs[lk + 6][lr] = b1.z; Bs[lk + 7][lr] = b1.w;
        __syncthreads();
#pragma unroll
        for (int kk = 0; kk < 16; kk++) {
            float a[8], bb[8];
            *(float4*)&a[0] = *(const float4*)&As[kk][ty * 4];
            *(float4*)&a[4] = *(const float4*)&As[kk][64 + ty * 4];
            *(float4*)&bb[0] = *(const float4*)&Bs[kk][tx * 4];
            *(float4*)&bb[4] = *(const float4*)&Bs[kk][64 + tx * 4];
#pragma unroll
            for (int i = 0; i < 8; i++)
#pragma unroll
                for (int j = 0; j < 8; j++) acc[i][j] += a[i] * bb[j];
        }
        __syncthreads();
    }

    int byte_mode = s_byte_mode;
    const size_t mbase = (size_t)b * L_ * L_;
#pragma unroll
    for (int ih = 0; ih < 2; ih++)
#pragma unroll
        for (int i = 0; i < 4; i++) {
            int r = row0 + ih * 64 + ty * 4 + i;
            const size_t rb = mbase + (size_t)r * L_;
#pragma unroll
            for (int jh = 0; jh < 2; jh++) {
                int c = col0 + jh * 64 + tx * 4;
                int m0, m1, m2, m3;
                if (byte_mode) {
                    uchar4 mu = *(const uchar4*)((const unsigned char*)mask + rb + c);
                    m0 = mu.x; m1 = mu.y; m2 = mu.z; m3 = mu.w;
                } else {
                    int4 mi = *(const int4*)((const int*)mask + rb + c);
                    m0 = mi.x; m1 = mi.y; m2 = mi.z; m3 = mi.w;
                }
                float4 o;
                o.x = m0 ? NEG_ : acc[ih * 4 + i][jh * 4 + 0] * 0.125f;
                o.y = m1 ? NEG_ : acc[ih * 4 + i][jh * 4 + 1] * 0.125f;
                o.z = m2 ? NEG_ : acc[ih * 4 + i][jh * 4 + 2] * 0.125f;
                o.w = m3 ? NEG_ : acc[ih * 4 + i][jh * 4 + 3] * 0.125f;
                *(float4*)&C[(size_t)r * L_ + c] = o;
            }
        }
}

// ============================================================================
// Fused softmax + AV.  One block = (z, 64 query rows).
// Phase 1: per-row max, then sum of exp (warp per 8 rows).
// Phase 2: stream 64-wide key chunks: p = exp(s-m)*inv -> write normalized
//          attn to gmem, stash p in smem, accumulate C[64x64] = P @ V.
// ============================================================================
__global__ __launch_bounds__(256) void softmax_av_kernel(
    float* __restrict__ attn, const float* __restrict__ vh,
    float* __restrict__ ctx)
{
    int row0 = blockIdx.x * 64;
    int z = blockIdx.y;
    int h = z / B_, b = z % B_;
    float* S = attn + (size_t)z * L_ * L_ + (size_t)row0 * L_;
    const float* Vb = vh + (size_t)(b * L_ * H_ + h) * DV_;

    __shared__ float Ps[64][68];
    __shared__ float Vs[64][68];
    __shared__ float sm_m[64], sm_inv[64];

    int tid = threadIdx.x;
    int warp = tid >> 5, lane = tid & 31;

    // ---- phase 1: row max, then sum of exp ----
    for (int rr = 0; rr < 8; rr++) {
        int r = warp * 8 + rr;
        const float4* row = (const float4*)(S + (size_t)r * L_);
        float m = -3.4e38f;
#pragma unroll
        for (int it = 0; it < 16; it++) {
            float4 vv = row[lane + it * 32];
            m = fmaxf(m, fmaxf(fmaxf(vv.x, vv.y), fmaxf(vv.z, vv.w)));
        }
#pragma unroll
        for (int o = 16; o; o >>= 1) m = fmaxf(m, __shfl_xor_sync(0xffffffffu, m, o));
        float s = 0.f;
#pragma unroll
        for (int it = 0; it < 16; it++) {
            float4 vv = row[lane + it * 32];
            s += __expf(vv.x - m) + __expf(vv.y - m)
               + __expf(vv.z - m) + __expf(vv.w - m);
        }
#pragma unroll
        for (int o = 16; o; o >>= 1) s += __shfl_xor_sync(0xffffffffu, s, o);
        if (lane == 0) { sm_m[r] = m; sm_inv[r] = 1.0f / s; }
    }
    __syncthreads();

    // ---- phase 2: normalize + write attn + accumulate AV ----
    int ty = tid >> 4, tx = tid & 15;
    float acc[4][4];
#pragma unroll
    for (int i = 0; i < 4; i++)
#pragma unroll
        for (int j = 0; j < 4; j++) acc[i][j] = 0.f;

    for (int k0 = 0; k0 < L_; k0 += 64) {
        // p tile: 64 rows x 64 keys; thread handles 4 float4s
#pragma unroll
        for (int i = 0; i < 4; i++) {
            int idx = tid + i * 256;          // 0..1023
            int r = idx >> 4;                 // 0..63
            int c4 = (idx & 15) * 4;          // 0..60
            float4 vv = *(const float4*)&S[(size_t)r * L_ + k0 + c4];
            float m = sm_m[r], inv = sm_inv[r];
            float4 p;
            p.x = __expf(vv.x - m) * inv;
            p.y = __expf(vv.y - m) * inv;
            p.z = __expf(vv.z - m) * inv;
            p.w = __expf(vv.w - m) * inv;
            *(float4*)&S[(size_t)r * L_ + k0 + c4] = p;
            *(float4*)&Ps[r][c4] = p;
        }
        // V tile: 64 keys x 64 dims
#pragma unroll
        for (int i = 0; i < 4; i++) {
            int idx = tid + i * 256;
            int kk = idx >> 4;
            int c4 = (idx & 15) * 4;
            *(float4*)&Vs[kk][c4] = *(const float4*)&Vb[(size_t)(k0 + kk) * (H_ * DV_) + c4];
        }
        __syncthreads();
#pragma unroll
        for (int kk = 0; kk < 64; kk++) {
            float a0 = Ps[ty * 4 + 0][kk];
            float a1 = Ps[ty * 4 + 1][kk];
            float a2 = Ps[ty * 4 + 2][kk];
            float a3 = Ps[ty * 4 + 3][kk];
            float4 bv = *(const float4*)&Vs[kk][tx * 4];
            acc[0][0] += a0 * bv.x; acc[0][1] += a0 * bv.y;
            acc[0][2] += a0 * bv.z; acc[0][3] += a0 * bv.w;
            acc[1][0] += a1 * bv.x; acc[1][1] += a1 * bv.y;
            acc[1][2] += a1 * bv.z; acc[1][3] += a1 * bv.w;
            acc[2][0] += a2 * bv.x; acc[2][1] += a2 * bv.y;
            acc[2][2] += a2 * bv.z; acc[2][3] += a2 * bv.w;
            acc[3][0] += a3 * bv.x; acc[3][1] += a3 * bv.y;
            acc[3][2] += a3 * bv.z; acc[3][3] += a3 * bv.w;
        }
        __syncthreads();
    }

    // epilogue: ctx[b, row0+r, h*64 + c]
#pragma unroll
    for (int i = 0; i < 4; i++) {
        int qrow = row0 + ty * 4 + i;
        float* Cp = ctx + ((size_t)(b * L_ + qrow) * (H_ * DV_)) + h * DV_ + tx * 4;
        *(float4*)Cp = make_float4(acc[i][0], acc[i][1], acc[i][2], acc[i][3]);
    }
}

// ============================================================================
// Residual add + LayerNorm. One block per row of 512, 256 threads x 2 elems.
// ============================================================================
__global__ void ln_kernel(const float* __restrict__ fc,
                          const float* __restrict__ resid,
                          const float* __restrict__ gamma,
                          const float* __restrict__ beta,
                          float* __restrict__ out)
{
    size_t base = (size_t)blockIdx.x * E_;
    int tid = threadIdx.x;
    float x0 = fc[base + tid] + resid[base + tid];
    float x1 = fc[base + tid + 256] + resid[base + tid + 256];
    float s = x0 + x1;
    float ss = x0 * x0 + x1 * x1;

    __shared__ float rs[8], rss[8];
#pragma unroll
    for (int o = 16; o; o >>= 1) {
        s  += __shfl_xor_sync(0xffffffffu, s, o);
        ss += __shfl_xor_sync(0xffffffffu, ss, o);
    }
    if ((tid & 31) == 0) { rs[tid >> 5] = s; rss[tid >> 5] = ss; }
    __syncthreads();
    s = 0.f; ss = 0.f;
#pragma unroll
    for (int i = 0; i < 8; i++) { s += rs[i]; ss += rss[i]; }

    float mu = s * (1.0f / E_);
    float var = ss * (1.0f / E_) - mu * mu;
    float rstd = rsqrtf(var + 1e-5f);
    out[base + tid]       = (x0 - mu) * rstd * gamma[tid] + beta[tid];
    out[base + tid + 256] = (x1 - mu) * rstd * gamma[tid + 256] + beta[tid + 256];
}

// ============================================================================
extern "C" void kernel_launch(void* const* d_in, const int* in_sizes, int n_in,
                              void* d_out, int out_size)
{
    const float* q    = (const float*)d_in[0];
    const float* k    = (const float*)d_in[1];
    const float* v    = (const float*)d_in[2];
    const void*  mask = (const void*)d_in[3];
    const float* Wq   = (const float*)d_in[4];
    const float* bq   = (const float*)d_in[5];
    const float* Wk   = (const float*)d_in[6];
    const float* bk   = (const float*)d_in[7];
    const float* Wv   = (const float*)d_in[8];
    const float* bv   = (const float*)d_in[9];
    const float* Wfc  = (const float*)d_in[10];
    const float* bfc  = (const float*)d_in[11];
    const float* gamma = (const float*)d_in[12];
    const float* beta  = (const float*)d_in[13];

    float* out  = (float*)d_out;                      // [B,L,E]
    float* attn = out + (size_t)B_ * L_ * E_;          // [H*B, L, L]

    float *qh, *kh, *vh, *ctx, *fc;
    cudaGetSymbolAddress((void**)&qh,  g_qh);
    cudaGetSymbolAddress((void**)&kh,  g_kh);
    cudaGetSymbolAddress((void**)&vh,  g_vh);
    cudaGetSymbolAddress((void**)&ctx, g_ctx);
    cudaGetSymbolAddress((void**)&fc,  g_fc);

    dim3 blk(256);

    // QKV projections: [8192,512] x3 in one launch
    dim3 gqkv((H_ * DK_) / 128, (B_ * L_) / 128, 3);   // (4, 64, 3)
    qkv_kernel<<<gqkv, blk>>>(q, k, v, Wq, bq, Wk, bk, Wv, bv, qh, kh, vh);

    // scores + mask -> attns region of d_out
    dim3 gsc(L_ / 128, L_ / 128, H_ * B_);             // (16, 16, 32)
    scores_kernel<<<gsc, blk>>>(qh, kh, mask, attn);

    // fused softmax (normalized attn written in place) + attn @ V
    dim3 gav(L_ / 64, H_ * B_);                        // (32, 32)
    softmax_av_kernel<<<gav, blk>>>(attn, vh, ctx);

    // FC
    dim3 gfc(E_ / 128, (B_ * L_) / 128);               // (4, 64)
    fc_kernel<<<gfc, blk>>>(ctx, Wfc, bfc, fc);

    // residual + LayerNorm -> outputs region of d_out
    ln_kernel<<<B_ * L_, 256>>>(fc, q, gamma, beta, out);
}

// round 5
// speedup vs baseline: 1.6280x; 1.0114x over previous
#include <cuda_runtime.h>
#include <cuda_bf16.h>
#include <cstdint>
#include <cstddef>

#define B_ 4
#define L_ 2048
#define E_ 512
#define H_ 8
#define DK_ 64
#define DV_ 64
#define NEG_ (-1e9f)

// ---- scratch (device globals; no allocations allowed) ----
__device__ float g_qh[B_ * L_ * H_ * DK_];
__device__ float g_kh[B_ * L_ * H_ * DK_];
__device__ float g_vh[B_ * L_ * H_ * DV_];
__device__ float g_ctx[B_ * L_ * H_ * DV_];
__device__ float g_fc[B_ * L_ * E_];
__device__ __nv_bfloat16 g_qhi[B_ * L_ * H_ * DK_];
__device__ __nv_bfloat16 g_qlo[B_ * L_ * H_ * DK_];
__device__ __nv_bfloat16 g_khi[B_ * L_ * H_ * DK_];
__device__ __nv_bfloat16 g_klo[B_ * L_ * H_ * DK_];
__device__ unsigned char g_mask8[B_ * L_ * L_];

// ============================================================================
// Scores via mma.sync m16n8k16 bf16 (2-term split, fp32 accum).
// One CTA = 128x128 tile of head z, 256 threads (8 warps).
// smem rows padded to 72 bf16 (144B) -> conflict-free fragment loads.
// ============================================================================
#define SCP 72   // padded row pitch in bf16 elems

__device__ __forceinline__ void mma16816(float* c, uint32_t a0, uint32_t a1,
                                         uint32_t a2, uint32_t a3,
                                         uint32_t b0, uint32_t b1) {
    asm volatile(
        "mma.sync.aligned.m16n8k16.row.col.f32.bf16.bf16.f32 "
        "{%0,%1,%2,%3}, {%4,%5,%6,%7}, {%8,%9}, {%0,%1,%2,%3};"
        : "+f"(c[0]), "+f"(c[1]), "+f"(c[2]), "+f"(c[3])
        : "r"(a0), "r"(a1), "r"(a2), "r"(a3), "r"(b0), "r"(b1));
}

__global__ __launch_bounds__(256, 2) void scores_mma_kernel(
    const __nv_bfloat16* __restrict__ qhi, const __nv_bfloat16* __restrict__ qlo,
    const __nv_bfloat16* __restrict__ khi, const __nv_bfloat16* __restrict__ klo,
    const unsigned char* __restrict__ mask8, float* __restrict__ attn)
{
    extern __shared__ __align__(16) char smem[];
    __nv_bfloat16* sQh = (__nv_bfloat16*)smem;
    __nv_bfloat16* sQl = sQh + 128 * SCP;
    __nv_bfloat16* sKh = sQl + 128 * SCP;
    __nv_bfloat16* sKl = sKh + 128 * SCP;

    int tid = threadIdx.x, lane = tid & 31, w = tid >> 5;
    int z = blockIdx.z, h = z / B_, b = z % B_;
    int row0 = blockIdx.y * 128, col0 = blockIdx.x * 128;

    // ---- cooperative loads: thread t loads half a row (32 bf16) of each ----
    {
        int r = tid >> 1, half = tid & 1;
        size_t qo = ((size_t)(b * L_ + row0 + r) * (H_ * DK_)) + h * DK_ + half * 32;
        size_t ko = ((size_t)(b * L_ + col0 + r) * (H_ * DK_)) + h * DK_ + half * 32;
        const uint4* gqh = (const uint4*)(qhi + qo);
        const uint4* gql = (const uint4*)(qlo + qo);
        const uint4* gkh = (const uint4*)(khi + ko);
        const uint4* gkl = (const uint4*)(klo + ko);
        uint4* sqh = (uint4*)(sQh + r * SCP + half * 32);
        uint4* sql = (uint4*)(sQl + r * SCP + half * 32);
        uint4* skh = (uint4*)(sKh + r * SCP + half * 32);
        uint4* skl = (uint4*)(sKl + r * SCP + half * 32);
#pragma unroll
        for (int i = 0; i < 4; i++) {
            sqh[i] = gqh[i]; sql[i] = gql[i];
            skh[i] = gkh[i]; skl[i] = gkl[i];
        }
    }
    __syncthreads();

    float acc[16][4];
#pragma unroll
    for (int nb = 0; nb < 16; nb++)
#pragma unroll
        for (int j = 0; j < 4; j++) acc[nb][j] = 0.f;

    int ar = w * 16 + (lane >> 2);
    int kc = (lane & 3) * 2;
    int bn = lane >> 2;

#pragma unroll
    for (int pass = 0; pass < 3; pass++) {
        const __nv_bfloat16* Ap = (pass == 2) ? sQl : sQh;
        const __nv_bfloat16* Bp = (pass == 1) ? sKl : sKh;
#pragma unroll
        for (int ks = 0; ks < 4; ks++) {
            int ak = ks * 16 + kc;
            uint32_t a0 = *(const uint32_t*)(Ap + ar * SCP + ak);
            uint32_t a1 = *(const uint32_t*)(Ap + (ar + 8) * SCP + ak);
            uint32_t a2 = *(const uint32_t*)(Ap + ar * SCP + ak + 8);
            uint32_t a3 = *(const uint32_t*)(Ap + (ar + 8) * SCP + ak + 8);
#pragma unroll
            for (int nb = 0; nb < 16; nb++) {
                uint32_t b0 = *(const uint32_t*)(Bp + (nb * 8 + bn) * SCP + ak);
                uint32_t b1 = *(const uint32_t*)(Bp + (nb * 8 + bn) * SCP + ak + 8);
                mma16816(acc[nb], a0, a1, a2, a3, b0, b1);
            }
        }
    }

    // ---- epilogue: scale, mask, store (two 8x... rows per fragment) ----
    int r0g = row0 + w * 16 + (lane >> 2);
    const size_t mb = (size_t)b * L_ * L_;
    const size_t ab = (size_t)z * L_ * L_;
#pragma unroll
    for (int nb = 0; nb < 16; nb++) {
        int cg = col0 + nb * 8 + (lane & 3) * 2;
        uchar2 m0 = *(const uchar2*)(mask8 + mb + (size_t)r0g * L_ + cg);
        uchar2 m1 = *(const uchar2*)(mask8 + mb + (size_t)(r0g + 8) * L_ + cg);
        float2 o0, o1;
        o0.x = m0.x ? NEG_ : acc[nb][0] * 0.125f;
        o0.y = m0.y ? NEG_ : acc[nb][1] * 0.125f;
        o1.x = m1.x ? NEG_ : acc[nb][2] * 0.125f;
        o1.y = m1.y ? NEG_ : acc[nb][3] * 0.125f;
        *(float2*)(attn + ab + (size_t)r0g * L_ + cg) = o0;
        *(float2*)(attn + ab + (size_t)(r0g + 8) * L_ + cg) = o1;
    }
}
#define SC_SMEM_BYTES (4 * 128 * SCP * 2)

// ============================================================================
// Split qh/kh into bf16 hi/lo pairs.
// ============================================================================
__global__ void split_qk_kernel(const float* __restrict__ qh,
                                const float* __restrict__ kh,
                                __nv_bfloat16* __restrict__ qhi,
                                __nv_bfloat16* __restrict__ qlo,
                                __nv_bfloat16* __restrict__ khi,
                                __nv_bfloat16* __restrict__ klo)
{
    size_t i = (size_t)(blockIdx.x * blockDim.x + threadIdx.x) * 4;
    float4 a = *(const float4*)(qh + i);
    float4 c = *(const float4*)(kh + i);
#pragma unroll
    for (int j = 0; j < 4; j++) {
        float va = ((const float*)&a)[j];
        __nv_bfloat16 hq = __float2bfloat16_rn(va);
        qhi[i + j] = hq;
        qlo[i + j] = __float2bfloat16_rn(va - __bfloat162float(hq));
        float vc = ((const float*)&c)[j];
        __nv_bfloat16 hk = __float2bfloat16_rn(vc);
        khi[i + j] = hk;
        klo[i + j] = __float2bfloat16_rn(vc - __bfloat162float(hk));
    }
}

// ============================================================================
// Mask -> uint8 (auto-detect int32 vs uint8 serialization).
// ============================================================================
__global__ void mask_conv_kernel(const void* __restrict__ mask,
                                 unsigned char* __restrict__ m8)
{
    __shared__ int s_byte;
    if (threadIdx.x == 0) {
        const unsigned int* mi = (const unsigned int*)mask;
        int bm = 0;
#pragma unroll 8
        for (int i = 0; i < 64; i++) if (mi[i] > 1u) bm = 1;
        s_byte = bm;
    }
    __syncthreads();
    size_t i = (size_t)blockIdx.x * blockDim.x + threadIdx.x;
    uchar4 o;
    if (s_byte) {
        uchar4 v = ((const uchar4*)mask)[i];
        o.x = v.x != 0; o.y = v.y != 0; o.z = v.z != 0; o.w = v.w != 0;
    } else {
        int4 v = ((const int4*)mask)[i];
        o.x = v.x != 0; o.y = v.y != 0; o.z = v.z != 0; o.w = v.w != 0;
    }
    ((uchar4*)m8)[i] = o;
}

// ============================================================================
// 128x128 fp32 GEMM body: C = A @ B^T + bias
// ============================================================================
__device__ __forceinline__ void gemm128_body(
    const float* __restrict__ A, int lda,
    const float* __restrict__ Bw, int ldb,
    float* __restrict__ C, int ldc,
    int K, const float* __restrict__ bias,
    int row0, int col0,
    float (&As)[16][132], float (&Bs)[16][132])
{
    int tid = threadIdx.x;
    int tx = tid & 15, ty = tid >> 4;
    int lr = tid >> 1;
    int lk = (tid & 1) * 8;
    float acc[8][8];
#pragma unroll
    for (int i = 0; i < 8; i++)
#pragma unroll
        for (int j = 0; j < 8; j++) acc[i][j] = 0.f;

    const float* Ap = A + (size_t)(row0 + lr) * lda + lk;
    const float* Bp = Bw + (size_t)(col0 + lr) * ldb + lk;

    for (int k0 = 0; k0 < K; k0 += 16) {
        float4 a0 = *(const float4*)(Ap + k0);
        float4 a1 = *(const float4*)(Ap + k0 + 4);
        float4 b0 = *(const float4*)(Bp + k0);
        float4 b1 = *(const float4*)(Bp + k0 + 4);
        As[lk + 0][lr] = a0.x; As[lk + 1][lr] = a0.y;
        As[lk + 2][lr] = a0.z; As[lk + 3][lr] = a0.w;
        As[lk + 4][lr] = a1.x; As[lk + 5][lr] = a1.y;
        As[lk + 6][lr] = a1.z; As[lk + 7][lr] = a1.w;
        Bs[lk + 0][lr] = b0.x; Bs[lk + 1][lr] = b0.y;
        Bs[lk + 2][lr] = b0.z; Bs[lk + 3][lr] = b0.w;
        Bs[lk + 4][lr] = b1.x; Bs[lk + 5][lr] = b1.y;
        Bs[lk + 6][lr] = b1.z; Bs[lk + 7][lr] = b1.w;
        __syncthreads();
#pragma unroll
        for (int kk = 0; kk < 16; kk++) {
            float a[8], b[8];
            *(float4*)&a[0] = *(const float4*)&As[kk][ty * 4];
            *(float4*)&a[4] = *(const float4*)&As[kk][64 + ty * 4];
            *(float4*)&b[0] = *(const float4*)&Bs[kk][tx * 4];
            *(float4*)&b[4] = *(const float4*)&Bs[kk][64 + tx * 4];
#pragma unroll
            for (int i = 0; i < 8; i++)
#pragma unroll
                for (int j = 0; j < 8; j++) acc[i][j] += a[i] * b[j];
        }
        __syncthreads();
    }

#pragma unroll
    for (int ih = 0; ih < 2; ih++)
#pragma unroll
        for (int i = 0; i < 4; i++) {
            int r = row0 + ih * 64 + ty * 4 + i;
#pragma unroll
            for (int jh = 0; jh < 2; jh++) {
                int c = col0 + jh * 64 + tx * 4;
                float4 bb = *(const float4*)&bias[c];
                float4 o;
                o.x = acc[ih * 4 + i][jh * 4 + 0] + bb.x;
                o.y = acc[ih * 4 + i][jh * 4 + 1] + bb.y;
                o.z = acc[ih * 4 + i][jh * 4 + 2] + bb.z;
                o.w = acc[ih * 4 + i][jh * 4 + 3] + bb.w;
                *(float4*)&C[(size_t)r * ldc + c] = o;
            }
        }
}

__global__ __launch_bounds__(256, 2) void qkv_kernel(
    const float* __restrict__ q, const float* __restrict__ k,
    const float* __restrict__ v,
    const float* __restrict__ Wq, const float* __restrict__ bq,
    const float* __restrict__ Wk, const float* __restrict__ bk,
    const float* __restrict__ Wv, const float* __restrict__ bv,
    float* __restrict__ qh, float* __restrict__ kh, float* __restrict__ vh)
{
    __shared__ float As[16][132];
    __shared__ float Bs[16][132];
    const float* A; const float* W; const float* bias; float* C;
    if (blockIdx.z == 0)      { A = q; W = Wq; bias = bq; C = qh; }
    else if (blockIdx.z == 1) { A = k; W = Wk; bias = bk; C = kh; }
    else                      { A = v; W = Wv; bias = bv; C = vh; }
    gemm128_body(A, E_, W, E_, C, H_ * DK_, E_, bias,
                 blockIdx.y * 128, blockIdx.x * 128, As, Bs);
}

__global__ __launch_bounds__(256, 2) void fc_kernel(
    const float* __restrict__ ctx, const float* __restrict__ Wfc,
    const float* __restrict__ bfc, float* __restrict__ fc)
{
    __shared__ float As[16][132];
    __shared__ float Bs[16][132];
    gemm128_body(ctx, H_ * DV_, Wfc, H_ * DV_, fc, E_, H_ * DV_, bfc,
                 blockIdx.y * 128, blockIdx.x * 128, As, Bs);
}

// ============================================================================
// Fused softmax + AV (no max pass; exp(-1e9) underflows to 0).
// ============================================================================
__global__ __launch_bounds__(256) void softmax_av_kernel(
    float* __restrict__ attn, const float* __restrict__ vh,
    float* __restrict__ ctx)
{
    int row0 = blockIdx.x * 64;
    int z = blockIdx.y;
    int h = z / B_, b = z % B_;
    float* S = attn + (size_t)z * L_ * L_ + (size_t)row0 * L_;
    const float* Vb = vh + (size_t)(b * L_ * H_ + h) * DV_;

    __shared__ float Ps[64][68];
    __shared__ float Vs[64][68];
    __shared__ float sm_inv[64];

    int tid = threadIdx.x;
    int warp = tid >> 5, lane = tid & 31;

    // ---- phase 1: exp in place + row sums ----
    for (int rr = 0; rr < 8; rr++) {
        int r = warp * 8 + rr;
        float4* row = (float4*)(S + (size_t)r * L_);
        float s = 0.f;
#pragma unroll
        for (int it = 0; it < 16; it++) {
            float4 vv = row[lane + it * 32];
            vv.x = __expf(vv.x); vv.y = __expf(vv.y);
            vv.z = __expf(vv.z); vv.w = __expf(vv.w);
            s += vv.x + vv.y + vv.z + vv.w;
            row[lane + it * 32] = vv;
        }
#pragma unroll
        for (int o = 16; o; o >>= 1) s += __shfl_xor_sync(0xffffffffu, s, o);
        if (lane == 0) sm_inv[r] = 1.0f / s;
    }
    __syncthreads();

    // ---- phase 2: normalize + write final attn + accumulate AV ----
    int ty = tid >> 4, tx = tid & 15;
    float acc[4][4];
#pragma unroll
    for (int i = 0; i < 4; i++)
#pragma unroll
        for (int j = 0; j < 4; j++) acc[i][j] = 0.f;

    for (int k0 = 0; k0 < L_; k0 += 64) {
#pragma unroll
        for (int i = 0; i < 4; i++) {
            int idx = tid + i * 256;
            int r = idx >> 4;
            int c4 = (idx & 15) * 4;
            float4 vv = *(const float4*)&S[(size_t)r * L_ + k0 + c4];
            float inv = sm_inv[r];
            float4 p;
            p.x = vv.x * inv; p.y = vv.y * inv;
            p.z = vv.z * inv; p.w = vv.w * inv;
            *(float4*)&S[(size_t)r * L_ + k0 + c4] = p;
            *(float4*)&Ps[r][c4] = p;
        }
#pragma unroll
        for (int i = 0; i < 4; i++) {
            int idx = tid + i * 256;
            int kk = idx >> 4;
            int c4 = (idx & 15) * 4;
            *(float4*)&Vs[kk][c4] = *(const float4*)&Vb[(size_t)(k0 + kk) * (H_ * DV_) + c4];
        }
        __syncthreads();
#pragma unroll
        for (int kk = 0; kk < 64; kk++) {
            float a0 = Ps[ty * 4 + 0][kk];
            float a1 = Ps[ty * 4 + 1][kk];
            float a2 = Ps[ty * 4 + 2][kk];
            float a3 = Ps[ty * 4 + 3][kk];
            float4 bv = *(const float4*)&Vs[kk][tx * 4];
            acc[0][0] += a0 * bv.x; acc[0][1] += a0 * bv.y;
            acc[0][2] += a0 * bv.z; acc[0][3] += a0 * bv.w;
            acc[1][0] += a1 * bv.x; acc[1][1] += a1 * bv.y;
            acc[1][2] += a1 * bv.z; acc[1][3] += a1 * bv.w;
            acc[2][0] += a2 * bv.x; acc[2][1] += a2 * bv.y;
            acc[2][2] += a2 * bv.z; acc[2][3] += a2 * bv.w;
            acc[3][0] += a3 * bv.x; acc[3][1] += a3 * bv.y;
            acc[3][2] += a3 * bv.z; acc[3][3] += a3 * bv.w;
        }
        __syncthreads();
    }

#pragma unroll
    for (int i = 0; i < 4; i++) {
        int qrow = row0 + ty * 4 + i;
        float* Cp = ctx + ((size_t)(b * L_ + qrow) * (H_ * DV_)) + h * DV_ + tx * 4;
        *(float4*)Cp = make_float4(acc[i][0], acc[i][1], acc[i][2], acc[i][3]);
    }
}

// ============================================================================
// Residual add + LayerNorm
// ============================================================================
__global__ void ln_kernel(const float* __restrict__ fc,
                          const float* __restrict__ resid,
                          const float* __restrict__ gamma,
                          const float* __restrict__ beta,
                          float* __restrict__ out)
{
    size_t base = (size_t)blockIdx.x * E_;
    int tid = threadIdx.x;
    float x0 = fc[base + tid] + resid[base + tid];
    float x1 = fc[base + tid + 256] + resid[base + tid + 256];
    float s = x0 + x1;
    float ss = x0 * x0 + x1 * x1;

    __shared__ float rs[8], rss[8];
#pragma unroll
    for (int o = 16; o; o >>= 1) {
        s  += __shfl_xor_sync(0xffffffffu, s, o);
        ss += __shfl_xor_sync(0xffffffffu, ss, o);
    }
    if ((tid & 31) == 0) { rs[tid >> 5] = s; rss[tid >> 5] = ss; }
    __syncthreads();
    s = 0.f; ss = 0.f;
#pragma unroll
    for (int i = 0; i < 8; i++) { s += rs[i]; ss += rss[i]; }

    float mu = s * (1.0f / E_);
    float var = ss * (1.0f / E_) - mu * mu;
    float rstd = rsqrtf(var + 1e-5f);
    out[base + tid]       = (x0 - mu) * rstd * gamma[tid] + beta[tid];
    out[base + tid + 256] = (x1 - mu) * rstd * gamma[tid + 256] + beta[tid + 256];
}

// ============================================================================
extern "C" void kernel_launch(void* const* d_in, const int* in_sizes, int n_in,
                              void* d_out, int out_size)
{
    const float* q    = (const float*)d_in[0];
    const float* k    = (const float*)d_in[1];
    const float* v    = (const float*)d_in[2];
    const void*  mask = (const void*)d_in[3];
    const float* Wq   = (const float*)d_in[4];
    const float* bq   = (const float*)d_in[5];
    const float* Wk   = (const float*)d_in[6];
    const float* bk   = (const float*)d_in[7];
    const float* Wv   = (const float*)d_in[8];
    const float* bv   = (const float*)d_in[9];
    const float* Wfc  = (const float*)d_in[10];
    const float* bfc  = (const float*)d_in[11];
    const float* gamma = (const float*)d_in[12];
    const float* beta  = (const float*)d_in[13];

    float* out  = (float*)d_out;                       // [B,L,E]
    float* attn = out + (size_t)B_ * L_ * E_;           // [H*B, L, L]

    float *qh, *kh, *vh, *ctx, *fc;
    __nv_bfloat16 *qhi, *qlo, *khi, *klo;
    unsigned char* m8;
    cudaGetSymbolAddress((void**)&qh,  g_qh);
    cudaGetSymbolAddress((void**)&kh,  g_kh);
    cudaGetSymbolAddress((void**)&vh,  g_vh);
    cudaGetSymbolAddress((void**)&ctx, g_ctx);
    cudaGetSymbolAddress((void**)&fc,  g_fc);
    cudaGetSymbolAddress((void**)&qhi, g_qhi);
    cudaGetSymbolAddress((void**)&qlo, g_qlo);
    cudaGetSymbolAddress((void**)&khi, g_khi);
    cudaGetSymbolAddress((void**)&klo, g_klo);
    cudaGetSymbolAddress((void**)&m8,  g_mask8);

    cudaFuncSetAttribute(scores_mma_kernel,
                         cudaFuncAttributeMaxDynamicSharedMemorySize, SC_SMEM_BYTES);

    dim3 blk(256);

    // mask -> uint8
    mask_conv_kernel<<<(B_ * L_ * L_) / (4 * 256), 256>>>(mask, m8);

    // QKV projections
    dim3 gqkv((H_ * DK_) / 128, (B_ * L_) / 128, 3);
    qkv_kernel<<<gqkv, blk>>>(q, k, v, Wq, bq, Wk, bk, Wv, bv, qh, kh, vh);

    // bf16 hi/lo split of qh, kh
    split_qk_kernel<<<(B_ * L_ * H_ * DK_) / (4 * 256), 256>>>(
        qh, kh, qhi, qlo, khi, klo);

    // scores via HMMA -> attns region of d_out
    dim3 gsc(L_ / 128, L_ / 128, H_ * B_);             // (16, 16, 32)
    scores_mma_kernel<<<gsc, blk, SC_SMEM_BYTES>>>(qhi, qlo, khi, klo, m8, attn);

    // fused softmax + AV
    dim3 gav(L_ / 64, H_ * B_);                        // (32, 32)
    softmax_av_kernel<<<gav, blk>>>(attn, vh, ctx);

    // FC
    dim3 gfc(E_ / 128, (B_ * L_) / 128);
    fc_kernel<<<gfc, blk>>>(ctx, Wfc, bfc, fc);

    // residual + LayerNorm
    ln_kernel<<<B_ * L_, 256>>>(fc, q, gamma, beta, out);
}

// round 6
// speedup vs baseline: 1.6552x; 1.0168x over previous
#include <cuda_runtime.h>
#include <cuda_bf16.h>
#include <cstdint>
#include <cstddef>

#define B_ 4
#define L_ 2048
#define E_ 512
#define H_ 8
#define DK_ 64
#define DV_ 64
#define NEG_ (-1e9f)
#define GP 72          // smem row pitch in bf16 elems (conflict-free for frags)

typedef __nv_bfloat16 bf16;
typedef __nv_bfloat162 bf162;

// ---- scratch (device globals; no allocations allowed) ----
__device__ float g_vh[B_ * L_ * E_];          // V projection, fp32
__device__ float g_fc[B_ * L_ * E_];          // FC output
__device__ bf16 g_qhi[B_ * L_ * E_];          // Q/K projections, hi/lo bf16
__device__ bf16 g_qlo[B_ * L_ * E_];
__device__ bf16 g_khi[B_ * L_ * E_];
__device__ bf16 g_klo[B_ * L_ * E_];
__device__ bf16 g_ihi[3 * B_ * L_ * E_];      // input splits (q,k,v)
__device__ bf16 g_ilo[3 * B_ * L_ * E_];
__device__ bf16 g_whi[4 * E_ * E_];           // weight splits (Wq,Wk,Wv,Wfc)
__device__ bf16 g_wlo[4 * E_ * E_];
__device__ bf16 g_ctxhi[B_ * L_ * E_];        // attn@V, hi/lo bf16
__device__ bf16 g_ctxlo[B_ * L_ * E_];
__device__ bf16 g_vhiT[B_ * H_ * DV_ * L_];   // V^T per (h,b): [z][n][k]
__device__ bf16 g_vloT[B_ * H_ * DV_ * L_];
__device__ unsigned char g_mask8[B_ * L_ * L_];

// ============================================================================
__device__ __forceinline__ void mma16816(float* c, uint32_t a0, uint32_t a1,
                                         uint32_t a2, uint32_t a3,
                                         uint32_t b0, uint32_t b1) {
    asm volatile(
        "mma.sync.aligned.m16n8k16.row.col.f32.bf16.bf16.f32 "
        "{%0,%1,%2,%3}, {%4,%5,%6,%7}, {%8,%9}, {%0,%1,%2,%3};"
        : "+f"(c[0]), "+f"(c[1]), "+f"(c[2]), "+f"(c[3])
        : "r"(a0), "r"(a1), "r"(a2), "r"(a3), "r"(b0), "r"(b1));
}

__device__ __forceinline__ void split2(float f, bf16& hi, bf16& lo) {
    hi = __float2bfloat16_rn(f);
    lo = __float2bfloat16_rn(f - __bfloat162float(hi));
}

// ============================================================================
// Generic HMMA NT GEMM body: C[128x128 tile] = A @ B^T (+bias).
// A[M,K], B[N,K] row-major, both given as hi/lo bf16 splits. 3-pass split MMA.
// Outputs: optional fp32 Cf and/or hi/lo bf16 Chi/Clo. 256 threads.
// ============================================================================
__device__ __forceinline__ void hmma_nt_body(
    const bf16* __restrict__ Ahi, const bf16* __restrict__ Alo,
    const bf16* __restrict__ Bhi, const bf16* __restrict__ Blo,
    const float* __restrict__ bias,
    float* __restrict__ Cf, bf16* __restrict__ Chi, bf16* __restrict__ Clo,
    int K, int ldc)
{
    extern __shared__ __align__(16) char smem[];
    bf16* sAh = (bf16*)smem;
    bf16* sAl = sAh + 128 * GP;
    bf16* sBh = sAl + 128 * GP;
    bf16* sBl = sBh + 128 * GP;

    int tid = threadIdx.x, lane = tid & 31, w = tid >> 5;
    int row0 = blockIdx.y * 128, col0 = blockIdx.x * 128;

    float acc[16][4];
#pragma unroll
    for (int nb = 0; nb < 16; nb++)
#pragma unroll
        for (int j = 0; j < 4; j++) acc[nb][j] = 0.f;

    int r = tid >> 1, half = tid & 1;
    const bf16* gAh = Ahi + (size_t)(row0 + r) * K + half * 32;
    const bf16* gAl = Alo + (size_t)(row0 + r) * K + half * 32;
    const bf16* gBh = Bhi + (size_t)(col0 + r) * K + half * 32;
    const bf16* gBl = Blo + (size_t)(col0 + r) * K + half * 32;
    bf16* dAh = sAh + r * GP + half * 32;
    bf16* dAl = sAl + r * GP + half * 32;
    bf16* dBh = sBh + r * GP + half * 32;
    bf16* dBl = sBl + r * GP + half * 32;

    int ar = w * 16 + (lane >> 2);
    int kc = (lane & 3) * 2;
    int bn = lane >> 2;

    for (int k0 = 0; k0 < K; k0 += 64) {
        __syncthreads();
        const uint4* a4h = (const uint4*)(gAh + k0);
        const uint4* a4l = (const uint4*)(gAl + k0);
        const uint4* b4h = (const uint4*)(gBh + k0);
        const uint4* b4l = (const uint4*)(gBl + k0);
#pragma unroll
        for (int i = 0; i < 4; i++) {
            ((uint4*)dAh)[i] = a4h[i];
            ((uint4*)dAl)[i] = a4l[i];
            ((uint4*)dBh)[i] = b4h[i];
            ((uint4*)dBl)[i] = b4l[i];
        }
        __syncthreads();
#pragma unroll
        for (int pass = 0; pass < 3; pass++) {
            const bf16* Ap = (pass == 2) ? sAl : sAh;
            const bf16* Bp = (pass == 1) ? sBl : sBh;
#pragma unroll
            for (int ks = 0; ks < 4; ks++) {
                int ak = ks * 16 + kc;
                uint32_t a0 = *(const uint32_t*)(Ap + ar * GP + ak);
                uint32_t a1 = *(const uint32_t*)(Ap + (ar + 8) * GP + ak);
                uint32_t a2 = *(const uint32_t*)(Ap + ar * GP + ak + 8);
                uint32_t a3 = *(const uint32_t*)(Ap + (ar + 8) * GP + ak + 8);
#pragma unroll
                for (int nb = 0; nb < 16; nb++) {
                    uint32_t b0 = *(const uint32_t*)(Bp + (nb * 8 + bn) * GP + ak);
                    uint32_t b1 = *(const uint32_t*)(Bp + (nb * 8 + bn) * GP + ak + 8);
                    mma16816(acc[nb], a0, a1, a2, a3, b0, b1);
                }
            }
        }
    }

    int r0g = row0 + w * 16 + (lane >> 2);
#pragma unroll
    for (int nb = 0; nb < 16; nb++) {
        int cg = col0 + nb * 8 + (lane & 3) * 2;
        float f00 = acc[nb][0] + bias[cg];
        float f01 = acc[nb][1] + bias[cg + 1];
        float f10 = acc[nb][2] + bias[cg];
        float f11 = acc[nb][3] + bias[cg + 1];
        if (Cf) {
            *(float2*)(Cf + (size_t)r0g * ldc + cg) = make_float2(f00, f01);
            *(float2*)(Cf + (size_t)(r0g + 8) * ldc + cg) = make_float2(f10, f11);
        }
        if (Chi) {
            bf162 h2, l2;
            split2(f00, h2.x, l2.x); split2(f01, h2.y, l2.y);
            *(bf162*)(Chi + (size_t)r0g * ldc + cg) = h2;
            *(bf162*)(Clo + (size_t)r0g * ldc + cg) = l2;
            split2(f10, h2.x, l2.x); split2(f11, h2.y, l2.y);
            *(bf162*)(Chi + (size_t)(r0g + 8) * ldc + cg) = h2;
            *(bf162*)(Clo + (size_t)(r0g + 8) * ldc + cg) = l2;
        }
    }
}
#define HMMA_SMEM (4 * 128 * GP * 2)

__global__ __launch_bounds__(256, 2) void qkv_hmma_kernel(
    const bf16* __restrict__ ihi, const bf16* __restrict__ ilo,
    const bf16* __restrict__ whi, const bf16* __restrict__ wlo,
    const float* __restrict__ bq, const float* __restrict__ bk,
    const float* __restrict__ bv,
    bf16* __restrict__ qhi, bf16* __restrict__ qlo,
    bf16* __restrict__ khi, bf16* __restrict__ klo,
    float* __restrict__ vh)
{
    int zz = blockIdx.z;
    const bf16* Ahi = ihi + (size_t)zz * (B_ * L_ * E_);
    const bf16* Alo = ilo + (size_t)zz * (B_ * L_ * E_);
    const bf16* Bhi = whi + (size_t)zz * (E_ * E_);
    const bf16* Blo = wlo + (size_t)zz * (E_ * E_);
    const float* bias = (zz == 0) ? bq : (zz == 1) ? bk : bv;
    float* Cf = (zz == 2) ? vh : nullptr;
    bf16* Chi = (zz == 0) ? qhi : (zz == 1) ? khi : nullptr;
    bf16* Clo = (zz == 0) ? qlo : (zz == 1) ? klo : nullptr;
    hmma_nt_body(Ahi, Alo, Bhi, Blo, bias, Cf, Chi, Clo, E_, E_);
}

__global__ __launch_bounds__(256, 2) void fc_hmma_kernel(
    const bf16* __restrict__ ctxhi, const bf16* __restrict__ ctxlo,
    const bf16* __restrict__ whi, const bf16* __restrict__ wlo,
    const float* __restrict__ bfc, float* __restrict__ fc)
{
    hmma_nt_body(ctxhi, ctxlo, whi + 3 * (E_ * E_), wlo + 3 * (E_ * E_),
                 bfc, fc, nullptr, nullptr, E_, E_);
}

// ============================================================================
// Scores via HMMA (unchanged from R5, validated).
// ============================================================================
__global__ __launch_bounds__(256, 2) void scores_mma_kernel(
    const bf16* __restrict__ qhi, const bf16* __restrict__ qlo,
    const bf16* __restrict__ khi, const bf16* __restrict__ klo,
    const unsigned char* __restrict__ mask8, float* __restrict__ attn)
{
    extern __shared__ __align__(16) char smem[];
    bf16* sQh = (bf16*)smem;
    bf16* sQl = sQh + 128 * GP;
    bf16* sKh = sQl + 128 * GP;
    bf16* sKl = sKh + 128 * GP;

    int tid = threadIdx.x, lane = tid & 31, w = tid >> 5;
    int z = blockIdx.z, h = z / B_, b = z % B_;
    int row0 = blockIdx.y * 128, col0 = blockIdx.x * 128;

    {
        int r = tid >> 1, half = tid & 1;
        size_t qo = ((size_t)(b * L_ + row0 + r) * E_) + h * DK_ + half * 32;
        size_t ko = ((size_t)(b * L_ + col0 + r) * E_) + h * DK_ + half * 32;
        const uint4* gqh = (const uint4*)(qhi + qo);
        const uint4* gql = (const uint4*)(qlo + qo);
        const uint4* gkh = (const uint4*)(khi + ko);
        const uint4* gkl = (const uint4*)(klo + ko);
        uint4* sqh = (uint4*)(sQh + r * GP + half * 32);
        uint4* sql = (uint4*)(sQl + r * GP + half * 32);
        uint4* skh = (uint4*)(sKh + r * GP + half * 32);
        uint4* skl = (uint4*)(sKl + r * GP + half * 32);
#pragma unroll
        for (int i = 0; i < 4; i++) {
            sqh[i] = gqh[i]; sql[i] = gql[i];
            skh[i] = gkh[i]; skl[i] = gkl[i];
        }
    }
    __syncthreads();

    float acc[16][4];
#pragma unroll
    for (int nb = 0; nb < 16; nb++)
#pragma unroll
        for (int j = 0; j < 4; j++) acc[nb][j] = 0.f;

    int ar = w * 16 + (lane >> 2);
    int kc = (lane & 3) * 2;
    int bn = lane >> 2;

#pragma unroll
    for (int pass = 0; pass < 3; pass++) {
        const bf16* Ap = (pass == 2) ? sQl : sQh;
        const bf16* Bp = (pass == 1) ? sKl : sKh;
#pragma unroll
        for (int ks = 0; ks < 4; ks++) {
            int ak = ks * 16 + kc;
            uint32_t a0 = *(const uint32_t*)(Ap + ar * GP + ak);
            uint32_t a1 = *(const uint32_t*)(Ap + (ar + 8) * GP + ak);
            uint32_t a2 = *(const uint32_t*)(Ap + ar * GP + ak + 8);
            uint32_t a3 = *(const uint32_t*)(Ap + (ar + 8) * GP + ak + 8);
#pragma unroll
            for (int nb = 0; nb < 16; nb++) {
                uint32_t b0 = *(const uint32_t*)(Bp + (nb * 8 + bn) * GP + ak);
                uint32_t b1 = *(const uint32_t*)(Bp + (nb * 8 + bn) * GP + ak + 8);
                mma16816(acc[nb], a0, a1, a2, a3, b0, b1);
            }
        }
    }

    int r0g = row0 + w * 16 + (lane >> 2);
    const size_t mb = (size_t)b * L_ * L_;
    const size_t ab = (size_t)z * L_ * L_;
#pragma unroll
    for (int nb = 0; nb < 16; nb++) {
        int cg = col0 + nb * 8 + (lane & 3) * 2;
        uchar2 m0 = *(const uchar2*)(mask8 + mb + (size_t)r0g * L_ + cg);
        uchar2 m1 = *(const uchar2*)(mask8 + mb + (size_t)(r0g + 8) * L_ + cg);
        float2 o0, o1;
        o0.x = m0.x ? NEG_ : acc[nb][0] * 0.125f;
        o0.y = m0.y ? NEG_ : acc[nb][1] * 0.125f;
        o1.x = m1.x ? NEG_ : acc[nb][2] * 0.125f;
        o1.y = m1.y ? NEG_ : acc[nb][3] * 0.125f;
        *(float2*)(attn + ab + (size_t)r0g * L_ + cg) = o0;
        *(float2*)(attn + ab + (size_t)(r0g + 8) * L_ + cg) = o1;
    }
}
#define SC_SMEM_BYTES (4 * 128 * GP * 2)

// ============================================================================
// Fused softmax + AV via HMMA. Block = 128 q-rows of one z.
// Phase 1: exp in place + row sums (no max pass; exp(-1e9)=0).
// Phase 2: per 64-key chunk: normalize -> final attn (fp32), hi/lo bf16 tile
//          in smem, 3-pass HMMA against pre-transposed hi/lo V.
// ============================================================================
__global__ __launch_bounds__(256) void softmax_av_kernel(
    float* __restrict__ attn,
    const bf16* __restrict__ vhiT, const bf16* __restrict__ vloT,
    bf16* __restrict__ ctxhi, bf16* __restrict__ ctxlo)
{
    extern __shared__ __align__(16) char smem[];
    bf16* sPh = (bf16*)smem;              // 128 x GP
    bf16* sPl = sPh + 128 * GP;
    bf16* sVh = sPl + 128 * GP;           // 64 x GP
    bf16* sVl = sVh + 64 * GP;
    float* sinv = (float*)(sVl + 64 * GP);

    int tid = threadIdx.x, lane = tid & 31, w = tid >> 5;
    int row0 = blockIdx.x * 128;
    int z = blockIdx.y, h = z / B_, b = z % B_;
    float* S = attn + (size_t)z * L_ * L_ + (size_t)row0 * L_;

    // ---- phase 1 ----
    for (int rr = 0; rr < 16; rr++) {
        int r = w * 16 + rr;
        float4* row = (float4*)(S + (size_t)r * L_);
        float s = 0.f;
#pragma unroll
        for (int it = 0; it < 16; it++) {
            float4 vv = row[lane + it * 32];
            vv.x = __expf(vv.x); vv.y = __expf(vv.y);
            vv.z = __expf(vv.z); vv.w = __expf(vv.w);
            s += vv.x + vv.y + vv.z + vv.w;
            row[lane + it * 32] = vv;
        }
#pragma unroll
        for (int o = 16; o; o >>= 1) s += __shfl_xor_sync(0xffffffffu, s, o);
        if (lane == 0) sinv[r] = 1.0f / s;
    }
    __syncthreads();

    // ---- phase 2 ----
    float acc[8][4];
#pragma unroll
    for (int nb = 0; nb < 8; nb++)
#pragma unroll
        for (int j = 0; j < 4; j++) acc[nb][j] = 0.f;

    int ar = w * 16 + (lane >> 2);
    int kc = (lane & 3) * 2;
    int bn = lane >> 2;

    for (int k0 = 0; k0 < L_; k0 += 64) {
        // P tile: normalize + write final attn + hi/lo into smem
#pragma unroll
        for (int i = 0; i < 8; i++) {
            int idx = tid + i * 256;
            int r = idx >> 4;
            int c4 = (idx & 15) * 4;
            float4 e = *(const float4*)(S + (size_t)r * L_ + k0 + c4);
            float inv = sinv[r];
            float4 p;
            p.x = e.x * inv; p.y = e.y * inv;
            p.z = e.z * inv; p.w = e.w * inv;
            *(float4*)(S + (size_t)r * L_ + k0 + c4) = p;
            bf162 h2, l2;
            split2(p.x, h2.x, l2.x); split2(p.y, h2.y, l2.y);
            *(bf162*)(sPh + r * GP + c4) = h2;
            *(bf162*)(sPl + r * GP + c4) = l2;
            split2(p.z, h2.x, l2.x); split2(p.w, h2.y, l2.y);
            *(bf162*)(sPh + r * GP + c4 + 2) = h2;
            *(bf162*)(sPl + r * GP + c4 + 2) = l2;
        }
        // V tile: [64 n][64 k] from transposed hi/lo
        {
            int n = tid >> 2, part = tid & 3;
            const uint4* gh = (const uint4*)(vhiT + ((size_t)z * DV_ + n) * L_ + k0 + part * 16);
            const uint4* gl = (const uint4*)(vloT + ((size_t)z * DV_ + n) * L_ + k0 + part * 16);
            uint4* dh = (uint4*)(sVh + n * GP + part * 16);
            uint4* dl = (uint4*)(sVl + n * GP + part * 16);
            dh[0] = gh[0]; dh[1] = gh[1];
            dl[0] = gl[0]; dl[1] = gl[1];
        }
        __syncthreads();
#pragma unroll
        for (int pass = 0; pass < 3; pass++) {
            const bf16* Ap = (pass == 2) ? sPl : sPh;
            const bf16* Bp = (pass == 1) ? sVl : sVh;
#pragma unroll
            for (int ks = 0; ks < 4; ks++) {
                int ak = ks * 16 + kc;
                uint32_t a0 = *(const uint32_t*)(Ap + ar * GP + ak);
                uint32_t a1 = *(const uint32_t*)(Ap + (ar + 8) * GP + ak);
                uint32_t a2 = *(const uint32_t*)(Ap + ar * GP + ak + 8);
                uint32_t a3 = *(const uint32_t*)(Ap + (ar + 8) * GP + ak + 8);
#pragma unroll
                for (int nb = 0; nb < 8; nb++) {
                    uint32_t b0 = *(const uint32_t*)(Bp + (nb * 8 + bn) * GP + ak);
                    uint32_t b1 = *(const uint32_t*)(Bp + (nb * 8 + bn) * GP + ak + 8);
                    mma16816(acc[nb], a0, a1, a2, a3, b0, b1);
                }
            }
        }
        __syncthreads();
    }

    // epilogue -> ctx hi/lo  [b, row, h*64 + c]
    int r0 = row0 + w * 16 + (lane >> 2);
#pragma unroll
    for (int nb = 0; nb < 8; nb++) {
        int cg = nb * 8 + (lane & 3) * 2;
        size_t o0 = ((size_t)(b * L_ + r0)) * E_ + h * DV_ + cg;
        size_t o1 = ((size_t)(b * L_ + r0 + 8)) * E_ + h * DV_ + cg;
        bf162 h2, l2;
        split2(acc[nb][0], h2.x, l2.x); split2(acc[nb][1], h2.y, l2.y);
        *(bf162*)(ctxhi + o0) = h2;
        *(bf162*)(ctxlo + o0) = l2;
        split2(acc[nb][2], h2.x, l2.x); split2(acc[nb][3], h2.y, l2.y);
        *(bf162*)(ctxhi + o1) = h2;
        *(bf162*)(ctxlo + o1) = l2;
    }
}
#define AV_SMEM (128 * GP * 2 * 2 + 64 * GP * 2 * 2 + 128 * 4)

// ============================================================================
// Input split: q,k,v fp32 -> hi/lo bf16
// ============================================================================
__global__ void split_in_kernel(const float* __restrict__ q,
                                const float* __restrict__ k,
                                const float* __restrict__ v,
                                bf16* __restrict__ ihi, bf16* __restrict__ ilo)
{
    int which = blockIdx.y;
    const float* src = (which == 0) ? q : (which == 1) ? k : v;
    bf16* hi = ihi + (size_t)which * (B_ * L_ * E_);
    bf16* lo = ilo + (size_t)which * (B_ * L_ * E_);
    size_t i = ((size_t)blockIdx.x * 256 + threadIdx.x) * 4;
    float4 a = *(const float4*)(src + i);
#pragma unroll
    for (int j = 0; j < 4; j++) {
        bf16 h, l;
        split2(((const float*)&a)[j], h, l);
        hi[i + j] = h; lo[i + j] = l;
    }
}

// Weight split: 4 x [512x512]
__global__ void split_w_kernel(const float* __restrict__ Wq,
                               const float* __restrict__ Wk,
                               const float* __restrict__ Wv,
                               const float* __restrict__ Wfc,
                               bf16* __restrict__ whi, bf16* __restrict__ wlo)
{
    int which = blockIdx.y;
    const float* src = (which == 0) ? Wq : (which == 1) ? Wk
                     : (which == 2) ? Wv : Wfc;
    bf16* hi = whi + (size_t)which * (E_ * E_);
    bf16* lo = wlo + (size_t)which * (E_ * E_);
    size_t i = ((size_t)blockIdx.x * 256 + threadIdx.x) * 4;
    float4 a = *(const float4*)(src + i);
#pragma unroll
    for (int j = 0; j < 4; j++) {
        bf16 h, l;
        split2(((const float*)&a)[j], h, l);
        hi[i + j] = h; lo[i + j] = l;
    }
}

// ============================================================================
// V transpose + split: vh [B,L,H*DV] fp32 -> vT [z][n(64)][k(2048)] hi/lo bf16
// ============================================================================
__global__ void vT_kernel(const float* __restrict__ vh,
                          bf16* __restrict__ vhiT, bf16* __restrict__ vloT)
{
    __shared__ float s[64][65];
    int z = blockIdx.x;            // h*B + b convention
    int h = z / B_, b = z % B_;
    int k0 = blockIdx.y * 64;
    int tid = threadIdx.x;
#pragma unroll
    for (int i = 0; i < 16; i++) {
        int idx = tid + i * 256;
        int kk = idx >> 6, n = idx & 63;
        s[kk][n] = vh[((size_t)(b * L_ + k0 + kk)) * E_ + h * DV_ + n];
    }
    __syncthreads();
#pragma unroll
    for (int i = 0; i < 16; i++) {
        int idx = tid + i * 256;
        int n = idx >> 6, kk = idx & 63;
        bf16 hi, lo;
        split2(s[kk][n], hi, lo);
        size_t o = ((size_t)z * DV_ + n) * L_ + k0 + kk;
        vhiT[o] = hi; vloT[o] = lo;
    }
}

// ============================================================================
// Mask -> uint8 (auto-detect int32 vs uint8 serialization).
// ============================================================================
__global__ void mask_conv_kernel(const void* __restrict__ mask,
                                 unsigned char* __restrict__ m8)
{
    __shared__ int s_byte;
    if (threadIdx.x == 0) {
        const unsigned int* mi = (const unsigned int*)mask;
        int bm = 0;
#pragma unroll 8
        for (int i = 0; i < 64; i++) if (mi[i] > 1u) bm = 1;
        s_byte = bm;
    }
    __syncthreads();
    size_t i = (size_t)blockIdx.x * blockDim.x + threadIdx.x;
    uchar4 o;
    if (s_byte) {
        uchar4 v = ((const uchar4*)mask)[i];
        o.x = v.x != 0; o.y = v.y != 0; o.z = v.z != 0; o.w = v.w != 0;
    } else {
        int4 v = ((const int4*)mask)[i];
        o.x = v.x != 0; o.y = v.y != 0; o.z = v.z != 0; o.w = v.w != 0;
    }
    ((uchar4*)m8)[i] = o;
}

// ============================================================================
// Residual add + LayerNorm
// ============================================================================
__global__ void ln_kernel(const float* __restrict__ fc,
                          const float* __restrict__ resid,
                          const float* __restrict__ gamma,
                          const float* __restrict__ beta,
                          float* __restrict__ out)
{
    size_t base = (size_t)blockIdx.x * E_;
    int tid = threadIdx.x;
    float x0 = fc[base + tid] + resid[base + tid];
    float x1 = fc[base + tid + 256] + resid[base + tid + 256];
    float s = x0 + x1;
    float ss = x0 * x0 + x1 * x1;

    __shared__ float rs[8], rss[8];
#pragma unroll
    for (int o = 16; o; o >>= 1) {
        s  += __shfl_xor_sync(0xffffffffu, s, o);
        ss += __shfl_xor_sync(0xffffffffu, ss, o);
    }
    if ((tid & 31) == 0) { rs[tid >> 5] = s; rss[tid >> 5] = ss; }
    __syncthreads();
    s = 0.f; ss = 0.f;
#pragma unroll
    for (int i = 0; i < 8; i++) { s += rs[i]; ss += rss[i]; }

    float mu = s * (1.0f / E_);
    float var = ss * (1.0f / E_) - mu * mu;
    float rstd = rsqrtf(var + 1e-5f);
    out[base + tid]       = (x0 - mu) * rstd * gamma[tid] + beta[tid];
    out[base + tid + 256] = (x1 - mu) * rstd * gamma[tid + 256] + beta[tid + 256];
}

// ============================================================================
extern "C" void kernel_launch(void* const* d_in, const int* in_sizes, int n_in,
                              void* d_out, int out_size)
{
    const float* q    = (const float*)d_in[0];
    const float* k    = (const float*)d_in[1];
    const float* v    = (const float*)d_in[2];
    const void*  mask = (const void*)d_in[3];
    const float* Wq   = (const float*)d_in[4];
    const float* bq   = (const float*)d_in[5];
    const float* Wk   = (const float*)d_in[6];
    const float* bk   = (const float*)d_in[7];
    const float* Wv   = (const float*)d_in[8];
    const float* bv   = (const float*)d_in[9];
    const float* Wfc  = (const float*)d_in[10];
    const float* bfc  = (const float*)d_in[11];
    const float* gamma = (const float*)d_in[12];
    const float* beta  = (const float*)d_in[13];

    float* out  = (float*)d_out;                       // [B,L,E]
    float* attn = out + (size_t)B_ * L_ * E_;           // [H*B, L, L]

    float *vh, *fc;
    bf16 *qhi, *qlo, *khi, *klo, *ihi, *ilo, *whi, *wlo;
    bf16 *ctxhi, *ctxlo, *vhiT, *vloT;
    unsigned char* m8;
    cudaGetSymbolAddress((void**)&vh,    g_vh);
    cudaGetSymbolAddress((void**)&fc,    g_fc);
    cudaGetSymbolAddress((void**)&qhi,   g_qhi);
    cudaGetSymbolAddress((void**)&qlo,   g_qlo);
    cudaGetSymbolAddress((void**)&khi,   g_khi);
    cudaGetSymbolAddress((void**)&klo,   g_klo);
    cudaGetSymbolAddress((void**)&ihi,   g_ihi);
    cudaGetSymbolAddress((void**)&ilo,   g_ilo);
    cudaGetSymbolAddress((void**)&whi,   g_whi);
    cudaGetSymbolAddress((void**)&wlo,   g_wlo);
    cudaGetSymbolAddress((void**)&ctxhi, g_ctxhi);
    cudaGetSymbolAddress((void**)&ctxlo, g_ctxlo);
    cudaGetSymbolAddress((void**)&vhiT,  g_vhiT);
    cudaGetSymbolAddress((void**)&vloT,  g_vloT);
    cudaGetSymbolAddress((void**)&m8,    g_mask8);

    cudaFuncSetAttribute(scores_mma_kernel,
                         cudaFuncAttributeMaxDynamicSharedMemorySize, SC_SMEM_BYTES);
    cudaFuncSetAttribute(qkv_hmma_kernel,
                         cudaFuncAttributeMaxDynamicSharedMemorySize, HMMA_SMEM);
    cudaFuncSetAttribute(fc_hmma_kernel,
                         cudaFuncAttributeMaxDynamicSharedMemorySize, HMMA_SMEM);
    cudaFuncSetAttribute(softmax_av_kernel,
                         cudaFuncAttributeMaxDynamicSharedMemorySize, AV_SMEM);

    // mask -> uint8
    mask_conv_kernel<<<(B_ * L_ * L_) / (4 * 256), 256>>>(mask, m8);

    // input + weight splits
    dim3 gsi((B_ * L_ * E_) / (4 * 256), 3);
    split_in_kernel<<<gsi, 256>>>(q, k, v, ihi, ilo);
    dim3 gsw((E_ * E_) / (4 * 256), 4);
    split_w_kernel<<<gsw, 256>>>(Wq, Wk, Wv, Wfc, whi, wlo);

    // QKV projections via HMMA (q/k emit hi/lo directly; v emits fp32)
    dim3 gqkv(E_ / 128, (B_ * L_) / 128, 3);
    qkv_hmma_kernel<<<gqkv, 256, HMMA_SMEM>>>(ihi, ilo, whi, wlo, bq, bk, bv,
                                              qhi, qlo, khi, klo, vh);

    // V transpose + split
    dim3 gvt(H_ * B_, L_ / 64);
    vT_kernel<<<gvt, 256>>>(vh, vhiT, vloT);

    // scores -> attns region of d_out
    dim3 gsc(L_ / 128, L_ / 128, H_ * B_);
    scores_mma_kernel<<<gsc, 256, SC_SMEM_BYTES>>>(qhi, qlo, khi, klo, m8, attn);

    // fused softmax + AV (HMMA) -> ctx hi/lo
    dim3 gav(L_ / 128, H_ * B_);
    softmax_av_kernel<<<gav, 256, AV_SMEM>>>(attn, vhiT, vloT, ctxhi, ctxlo);

    // FC via HMMA
    dim3 gfc(E_ / 128, (B_ * L_) / 128);
    fc_hmma_kernel<<<gfc, 256, HMMA_SMEM>>>(ctxhi, ctxlo, whi, wlo, bfc, fc);

    // residual + LayerNorm
    ln_kernel<<<B_ * L_, 256>>>(fc, q, gamma, beta, out);
}

// round 9
// speedup vs baseline: 2.2624x; 1.3668x over previous
#include <cuda_runtime.h>
#include <cuda_bf16.h>
#include <cstdint>
#include <cstddef>

#define B_ 4
#define L_ 2048
#define E_ 512
#define H_ 8
#define DK_ 64
#define DV_ 64
#define GP 72          // smem pitch (bf16) for 64-wide operand tiles
#define PV 136         // smem pitch (bf16) for 128-wide P / V tiles

typedef __nv_bfloat16 bf16;
typedef __nv_bfloat162 bf162;

// ---- scratch (device globals; no allocations allowed) ----
__device__ float g_vh[B_ * L_ * E_];
__device__ float g_fc[B_ * L_ * E_];
__device__ bf16 g_qhi[B_ * L_ * E_];
__device__ bf16 g_qlo[B_ * L_ * E_];
__device__ bf16 g_khi[B_ * L_ * E_];
__device__ bf16 g_klo[B_ * L_ * E_];
__device__ bf16 g_ihi[3 * B_ * L_ * E_];
__device__ bf16 g_ilo[3 * B_ * L_ * E_];
__device__ bf16 g_whi[4 * E_ * E_];
__device__ bf16 g_wlo[4 * E_ * E_];
__device__ bf16 g_ctxhi[B_ * L_ * E_];
__device__ bf16 g_ctxlo[B_ * L_ * E_];
__device__ bf16 g_vhiT[B_ * H_ * DV_ * L_];   // [z][n(64)][k(2048)]
__device__ bf16 g_vloT[B_ * H_ * DV_ * L_];
__device__ unsigned char g_mask8[B_ * L_ * L_];

// ============================================================================
__device__ __forceinline__ void mma16816(float* c, uint32_t a0, uint32_t a1,
                                         uint32_t a2, uint32_t a3,
                                         uint32_t b0, uint32_t b1) {
    asm volatile(
        "mma.sync.aligned.m16n8k16.row.col.f32.bf16.bf16.f32 "
        "{%0,%1,%2,%3}, {%4,%5,%6,%7}, {%8,%9}, {%0,%1,%2,%3};"
        : "+f"(c[0]), "+f"(c[1]), "+f"(c[2]), "+f"(c[3])
        : "r"(a0), "r"(a1), "r"(a2), "r"(a3), "r"(b0), "r"(b1));
}

__device__ __forceinline__ void split2(float f, bf16& hi, bf16& lo) {
    hi = __float2bfloat16_rn(f);
    lo = __float2bfloat16_rn(f - __bfloat162float(hi));
}

// ============================================================================
// Fused attention: scores (HMMA hi/lo) + mask + exp + rowsum + AV (HMMA)
// + in-place normalization of the attn slab + ctx output.
// CTA = 128 q-rows of one z = h*B + b. 256 threads.
// ============================================================================
__global__ __launch_bounds__(256, 1) void attn_fused_kernel(
    const bf16* __restrict__ qhi, const bf16* __restrict__ qlo,
    const bf16* __restrict__ khi, const bf16* __restrict__ klo,
    const bf16* __restrict__ vhiT, const bf16* __restrict__ vloT,
    const unsigned char* __restrict__ mask8,
    float* __restrict__ attn,
    bf16* __restrict__ ctxhi, bf16* __restrict__ ctxlo)
{
    extern __shared__ __align__(16) char smem[];
    bf16* sQh = (bf16*)smem;                  // 128 x GP
    bf16* sQl = sQh + 128 * GP;
    bf16* sKh = sQl + 128 * GP;               // 128 x GP
    bf16* sKl = sKh + 128 * GP;
    bf16* sPh = sKl + 128 * GP;               // 128 x PV
    bf16* sPl = sPh + 128 * PV;
    bf16* sVh = sPl + 128 * PV;               // 64 x PV
    bf16* sVl = sVh + 64 * PV;
    float* sinv = (float*)(sVl + 64 * PV);    // 128

    int tid = threadIdx.x, lane = tid & 31, w = tid >> 5;
    int row0 = blockIdx.x * 128;
    int z = blockIdx.y, h = z / B_, b = z % B_;

    // ---- Q tile (persistent) ----
    {
        int r = tid >> 1, half = tid & 1;
        size_t qo = ((size_t)(b * L_ + row0 + r) * E_) + h * DK_ + half * 32;
        const uint4* gqh = (const uint4*)(qhi + qo);
        const uint4* gql = (const uint4*)(qlo + qo);
        uint4* dqh = (uint4*)(sQh + r * GP + half * 32);
        uint4* dql = (uint4*)(sQl + r * GP + half * 32);
#pragma unroll
        for (int i = 0; i < 4; i++) { dqh[i] = gqh[i]; dql[i] = gql[i]; }
    }

    int ar = w * 16 + (lane >> 2);     // local q row for A fragments
    int kc = (lane & 3) * 2;
    int bn = lane >> 2;
    int lr0 = w * 16 + (lane >> 2);    // epilogue rows lr0, lr0+8
    int r0g = row0 + lr0;

    float accv[8][4];
#pragma unroll
    for (int nb = 0; nb < 8; nb++)
#pragma unroll
        for (int j = 0; j < 4; j++) accv[nb][j] = 0.f;
    float rs0 = 0.f, rs1 = 0.f;

    const size_t mb = (size_t)b * L_ * L_;
    float* Az = attn + (size_t)z * L_ * L_;

    for (int kt = 0; kt < 16; kt++) {
        int k0 = kt * 128;
        __syncthreads();   // prior-iter MMA reads of sK/sV complete
        // ---- K tile: 128 keys x 64 dk ----
        {
            int r = tid >> 1, half = tid & 1;
            size_t ko = ((size_t)(b * L_ + k0 + r) * E_) + h * DK_ + half * 32;
            const uint4* gkh = (const uint4*)(khi + ko);
            const uint4* gkl = (const uint4*)(klo + ko);
            uint4* dkh = (uint4*)(sKh + r * GP + half * 32);
            uint4* dkl = (uint4*)(sKl + r * GP + half * 32);
#pragma unroll
            for (int i = 0; i < 4; i++) { dkh[i] = gkh[i]; dkl[i] = gkl[i]; }
        }
        // ---- V^T tile: 64 dv x 128 keys ----
        {
            int n = tid >> 2, part = tid & 3;
            const uint4* gh = (const uint4*)(vhiT + ((size_t)z * DV_ + n) * L_ + k0 + part * 32);
            const uint4* gl = (const uint4*)(vloT + ((size_t)z * DV_ + n) * L_ + k0 + part * 32);
            uint4* dh = (uint4*)(sVh + n * PV + part * 32);
            uint4* dl = (uint4*)(sVl + n * PV + part * 32);
#pragma unroll
            for (int i = 0; i < 4; i++) { dh[i] = gh[i]; dl[i] = gl[i]; }
        }
        __syncthreads();

        // ---- scores: 128x128 tile, 3-pass hi/lo ----
        float acc[16][4];
#pragma unroll
        for (int nb = 0; nb < 16; nb++)
#pragma unroll
            for (int j = 0; j < 4; j++) acc[nb][j] = 0.f;
#pragma unroll
        for (int pass = 0; pass < 3; pass++) {
            const bf16* Ap = (pass == 2) ? sQl : sQh;
            const bf16* Bp = (pass == 1) ? sKl : sKh;
#pragma unroll
            for (int ks = 0; ks < 4; ks++) {
                int ak = ks * 16 + kc;
                uint32_t a0 = *(const uint32_t*)(Ap + ar * GP + ak);
                uint32_t a1 = *(const uint32_t*)(Ap + (ar + 8) * GP + ak);
                uint32_t a2 = *(const uint32_t*)(Ap + ar * GP + ak + 8);
                uint32_t a3 = *(const uint32_t*)(Ap + (ar + 8) * GP + ak + 8);
#pragma unroll
                for (int nb = 0; nb < 16; nb++) {
                    uint32_t b0 = *(const uint32_t*)(Bp + (nb * 8 + bn) * GP + ak);
                    uint32_t b1 = *(const uint32_t*)(Bp + (nb * 8 + bn) * GP + ak + 8);
                    mma16816(acc[nb], a0, a1, a2, a3, b0, b1);
                }
            }
        }

        // ---- mask + scale + exp -> gmem (unnormalized) + smem P hi/lo ----
#pragma unroll
        for (int nb = 0; nb < 16; nb++) {
            int cl = nb * 8 + (lane & 3) * 2;
            int cg = k0 + cl;
            uchar2 m0 = *(const uchar2*)(mask8 + mb + (size_t)r0g * L_ + cg);
            uchar2 m1 = *(const uchar2*)(mask8 + mb + (size_t)(r0g + 8) * L_ + cg);
            float e00 = m0.x ? 0.f : __expf(acc[nb][0] * 0.125f);
            float e01 = m0.y ? 0.f : __expf(acc[nb][1] * 0.125f);
            float e10 = m1.x ? 0.f : __expf(acc[nb][2] * 0.125f);
            float e11 = m1.y ? 0.f : __expf(acc[nb][3] * 0.125f);
            *(float2*)(Az + (size_t)r0g * L_ + cg) = make_float2(e00, e01);
            *(float2*)(Az + (size_t)(r0g + 8) * L_ + cg) = make_float2(e10, e11);
            rs0 += e00 + e01;
            rs1 += e10 + e11;
            bf162 h2, l2;
            split2(e00, h2.x, l2.x); split2(e01, h2.y, l2.y);
            *(bf162*)(sPh + lr0 * PV + cl) = h2;
            *(bf162*)(sPl + lr0 * PV + cl) = l2;
            split2(e10, h2.x, l2.x); split2(e11, h2.y, l2.y);
            *(bf162*)(sPh + (lr0 + 8) * PV + cl) = h2;
            *(bf162*)(sPl + (lr0 + 8) * PV + cl) = l2;
        }
        __syncwarp();   // P rows are warp-local (warp w owns rows w*16..+15)

        // ---- AV: accv += P(128x128) @ V^T(64x128)^T ----
#pragma unroll
        for (int pass = 0; pass < 3; pass++) {
            const bf16* Ap = (pass == 2) ? sPl : sPh;
            const bf16* Bp = (pass == 1) ? sVl : sVh;
#pragma unroll
            for (int ks = 0; ks < 8; ks++) {
                int ak = ks * 16 + kc;
                uint32_t a0 = *(const uint32_t*)(Ap + ar * PV + ak);
                uint32_t a1 = *(const uint32_t*)(Ap + (ar + 8) * PV + ak);
                uint32_t a2 = *(const uint32_t*)(Ap + ar * PV + ak + 8);
                uint32_t a3 = *(const uint32_t*)(Ap + (ar + 8) * PV + ak + 8);
#pragma unroll
                for (int nb = 0; nb < 8; nb++) {
                    uint32_t b0 = *(const uint32_t*)(Bp + (nb * 8 + bn) * PV + ak);
                    uint32_t b1 = *(const uint32_t*)(Bp + (nb * 8 + bn) * PV + ak + 8);
                    mma16816(accv[nb], a0, a1, a2, a3, b0, b1);
                }
            }
        }
    }

    // ---- rowsums -> sinv ----
    rs0 += __shfl_xor_sync(0xffffffffu, rs0, 1);
    rs0 += __shfl_xor_sync(0xffffffffu, rs0, 2);
    rs1 += __shfl_xor_sync(0xffffffffu, rs1, 1);
    rs1 += __shfl_xor_sync(0xffffffffu, rs1, 2);
    if ((lane & 3) == 0) {
        sinv[lr0] = 1.0f / rs0;
        sinv[lr0 + 8] = 1.0f / rs1;
    }
    __syncthreads();

    // ---- ctx epilogue: accv * inv -> hi/lo bf16 ----
    {
        float inv0 = sinv[lr0], inv1 = sinv[lr0 + 8];
#pragma unroll
        for (int nb = 0; nb < 8; nb++) {
            int cg = nb * 8 + (lane & 3) * 2;
            size_t o0 = ((size_t)(b * L_ + r0g)) * E_ + h * DV_ + cg;
            size_t o1 = ((size_t)(b * L_ + r0g + 8)) * E_ + h * DV_ + cg;
            bf162 h2, l2;
            split2(accv[nb][0] * inv0, h2.x, l2.x);
            split2(accv[nb][1] * inv0, h2.y, l2.y);
            *(bf162*)(ctxhi + o0) = h2;
            *(bf162*)(ctxlo + o0) = l2;
            split2(accv[nb][2] * inv1, h2.x, l2.x);
            split2(accv[nb][3] * inv1, h2.y, l2.y);
            *(bf162*)(ctxhi + o1) = h2;
            *(bf162*)(ctxlo + o1) = l2;
        }
    }

    // ---- normalization sweep over this CTA's slab (coalesced float4) ----
    {
        float4* A4 = (float4*)(Az + (size_t)row0 * L_);
#pragma unroll 4
        for (int i = 0; i < 256; i++) {
            int gi = tid + i * 256;          // 0..65535 float4 index
            int r = gi >> 9;                 // 512 float4 per row
            float inv = sinv[r];
            float4 v = A4[gi];
            v.x *= inv; v.y *= inv; v.z *= inv; v.w *= inv;
            A4[gi] = v;
        }
    }
}
#define AF_SMEM (2*128*GP*2 + 2*128*GP*2/2*0 + 128*GP*2*2 + 128*PV*2*2 + 64*PV*2*2 + 128*4)
// explicit: Q(2*128*72*2=36864) + K(36864) + P(2*128*136*2=69632) + V(2*64*136*2=34816) + 512
#define AF_SMEM_BYTES (36864 + 36864 + 69632 + 34816 + 512)

// ============================================================================
// Generic HMMA NT GEMM body (validated R6): C = A @ B^T + bias
// ============================================================================
__device__ __forceinline__ void hmma_nt_body(
    const bf16* __restrict__ Ahi, const bf16* __restrict__ Alo,
    const bf16* __restrict__ Bhi, const bf16* __restrict__ Blo,
    const float* __restrict__ bias,
    float* __restrict__ Cf, bf16* __restrict__ Chi, bf16* __restrict__ Clo,
    int K, int ldc)
{
    extern __shared__ __align__(16) char smem[];
    bf16* sAh = (bf16*)smem;
    bf16* sAl = sAh + 128 * GP;
    bf16* sBh = sAl + 128 * GP;
    bf16* sBl = sBh + 128 * GP;

    int tid = threadIdx.x, lane = tid & 31, w = tid >> 5;
    int row0 = blockIdx.y * 128, col0 = blockIdx.x * 128;

    float acc[16][4];
#pragma unroll
    for (int nb = 0; nb < 16; nb++)
#pragma unroll
        for (int j = 0; j < 4; j++) acc[nb][j] = 0.f;

    int r = tid >> 1, half = tid & 1;
    const bf16* gAh = Ahi + (size_t)(row0 + r) * K + half * 32;
    const bf16* gAl = Alo + (size_t)(row0 + r) * K + half * 32;
    const bf16* gBh = Bhi + (size_t)(col0 + r) * K + half * 32;
    const bf16* gBl = Blo + (size_t)(col0 + r) * K + half * 32;
    bf16* dAh = sAh + r * GP + half * 32;
    bf16* dAl = sAl + r * GP + half * 32;
    bf16* dBh = sBh + r * GP + half * 32;
    bf16* dBl = sBl + r * GP + half * 32;

    int ar = w * 16 + (lane >> 2);
    int kc = (lane & 3) * 2;
    int bn = lane >> 2;

    for (int k0 = 0; k0 < K; k0 += 64) {
        __syncthreads();
        const uint4* a4h = (const uint4*)(gAh + k0);
        const uint4* a4l = (const uint4*)(gAl + k0);
        const uint4* b4h = (const uint4*)(gBh + k0);
        const uint4* b4l = (const uint4*)(gBl + k0);
#pragma unroll
        for (int i = 0; i < 4; i++) {
            ((uint4*)dAh)[i] = a4h[i];
            ((uint4*)dAl)[i] = a4l[i];
            ((uint4*)dBh)[i] = b4h[i];
            ((uint4*)dBl)[i] = b4l[i];
        }
        __syncthreads();
#pragma unroll
        for (int pass = 0; pass < 3; pass++) {
            const bf16* Ap = (pass == 2) ? sAl : sAh;
            const bf16* Bp = (pass == 1) ? sBl : sBh;
#pragma unroll
            for (int ks = 0; ks < 4; ks++) {
                int ak = ks * 16 + kc;
                uint32_t a0 = *(const uint32_t*)(Ap + ar * GP + ak);
                uint32_t a1 = *(const uint32_t*)(Ap + (ar + 8) * GP + ak);
                uint32_t a2 = *(const uint32_t*)(Ap + ar * GP + ak + 8);
                uint32_t a3 = *(const uint32_t*)(Ap + (ar + 8) * GP + ak + 8);
#pragma unroll
                for (int nb = 0; nb < 16; nb++) {
                    uint32_t b0 = *(const uint32_t*)(Bp + (nb * 8 + bn) * GP + ak);
                    uint32_t b1 = *(const uint32_t*)(Bp + (nb * 8 + bn) * GP + ak + 8);
                    mma16816(acc[nb], a0, a1, a2, a3, b0, b1);
                }
            }
        }
    }

    int r0g = row0 + w * 16 + (lane >> 2);
#pragma unroll
    for (int nb = 0; nb < 16; nb++) {
        int cg = col0 + nb * 8 + (lane & 3) * 2;
        float f00 = acc[nb][0] + bias[cg];
        float f01 = acc[nb][1] + bias[cg + 1];
        float f10 = acc[nb][2] + bias[cg];
        float f11 = acc[nb][3] + bias[cg + 1];
        if (Cf) {
            *(float2*)(Cf + (size_t)r0g * ldc + cg) = make_float2(f00, f01);
            *(float2*)(Cf + (size_t)(r0g + 8) * ldc + cg) = make_float2(f10, f11);
        }
        if (Chi) {
            bf162 h2, l2;
            split2(f00, h2.x, l2.x); split2(f01, h2.y, l2.y);
            *(bf162*)(Chi + (size_t)r0g * ldc + cg) = h2;
            *(bf162*)(Clo + (size_t)r0g * ldc + cg) = l2;
            split2(f10, h2.x, l2.x); split2(f11, h2.y, l2.y);
            *(bf162*)(Chi + (size_t)(r0g + 8) * ldc + cg) = h2;
            *(bf162*)(Clo + (size_t)(r0g + 8) * ldc + cg) = l2;
        }
    }
}
#define HMMA_SMEM (4 * 128 * GP * 2)

__global__ __launch_bounds__(256, 2) void qkv_hmma_kernel(
    const bf16* __restrict__ ihi, const bf16* __restrict__ ilo,
    const bf16* __restrict__ whi, const bf16* __restrict__ wlo,
    const float* __restrict__ bq, const float* __restrict__ bk,
    const float* __restrict__ bv,
    bf16* __restrict__ qhi, bf16* __restrict__ qlo,
    bf16* __restrict__ khi, bf16* __restrict__ klo,
    float* __restrict__ vh)
{
    int zz = blockIdx.z;
    const bf16* Ahi = ihi + (size_t)zz * (B_ * L_ * E_);
    const bf16* Alo = ilo + (size_t)zz * (B_ * L_ * E_);
    const bf16* Bhi = whi + (size_t)zz * (E_ * E_);
    const bf16* Blo = wlo + (size_t)zz * (E_ * E_);
    const float* bias = (zz == 0) ? bq : (zz == 1) ? bk : bv;
    float* Cf = (zz == 2) ? vh : nullptr;
    bf16* Chi = (zz == 0) ? qhi : (zz == 1) ? khi : nullptr;
    bf16* Clo = (zz == 0) ? qlo : (zz == 1) ? klo : nullptr;
    hmma_nt_body(Ahi, Alo, Bhi, Blo, bias, Cf, Chi, Clo, E_, E_);
}

__global__ __launch_bounds__(256, 2) void fc_hmma_kernel(
    const bf16* __restrict__ ctxhi, const bf16* __restrict__ ctxlo,
    const bf16* __restrict__ whi, const bf16* __restrict__ wlo,
    const float* __restrict__ bfc, float* __restrict__ fc)
{
    hmma_nt_body(ctxhi, ctxlo, whi + 3 * (E_ * E_), wlo + 3 * (E_ * E_),
                 bfc, fc, nullptr, nullptr, E_, E_);
}

// ============================================================================
// Input / weight splits
// ============================================================================
__global__ void split_in_kernel(const float* __restrict__ q,
                                const float* __restrict__ k,
                                const float* __restrict__ v,
                                bf16* __restrict__ ihi, bf16* __restrict__ ilo)
{
    int which = blockIdx.y;
    const float* src = (which == 0) ? q : (which == 1) ? k : v;
    bf16* hi = ihi + (size_t)which * (B_ * L_ * E_);
    bf16* lo = ilo + (size_t)which * (B_ * L_ * E_);
    size_t i = ((size_t)blockIdx.x * 256 + threadIdx.x) * 4;
    float4 a = *(const float4*)(src + i);
#pragma unroll
    for (int j = 0; j < 4; j++) {
        bf16 h, l;
        split2(((const float*)&a)[j], h, l);
        hi[i + j] = h; lo[i + j] = l;
    }
}

__global__ void split_w_kernel(const float* __restrict__ Wq,
                               const float* __restrict__ Wk,
                               const float* __restrict__ Wv,
                               const float* __restrict__ Wfc,
                               bf16* __restrict__ whi, bf16* __restrict__ wlo)
{
    int which = blockIdx.y;
    const float* src = (which == 0) ? Wq : (which == 1) ? Wk
                     : (which == 2) ? Wv : Wfc;
    bf16* hi = whi + (size_t)which * (E_ * E_);
    bf16* lo = wlo + (size_t)which * (E_ * E_);
    size_t i = ((size_t)blockIdx.x * 256 + threadIdx.x) * 4;
    float4 a = *(const float4*)(src + i);
#pragma unroll
    for (int j = 0; j < 4; j++) {
        bf16 h, l;
        split2(((const float*)&a)[j], h, l);
        hi[i + j] = h; lo[i + j] = l;
    }
}

// ============================================================================
// V transpose + split
// ============================================================================
__global__ void vT_kernel(const float* __restrict__ vh,
                          bf16* __restrict__ vhiT, bf16* __restrict__ vloT)
{
    __shared__ float s[64][65];
    int z = blockIdx.x;
    int h = z / B_, b = z % B_;
    int k0 = blockIdx.y * 64;
    int tid = threadIdx.x;
#pragma unroll
    for (int i = 0; i < 16; i++) {
        int idx = tid + i * 256;
        int kk = idx >> 6, n = idx & 63;
        s[kk][n] = vh[((size_t)(b * L_ + k0 + kk)) * E_ + h * DV_ + n];
    }
    __syncthreads();
#pragma unroll
    for (int i = 0; i < 16; i++) {
        int idx = tid + i * 256;
        int n = idx >> 6, kk = idx & 63;
        bf16 hi, lo;
        split2(s[kk][n], hi, lo);
        size_t o = ((size_t)z * DV_ + n) * L_ + k0 + kk;
        vhiT[o] = hi; vloT[o] = lo;
    }
}

// ============================================================================
// Mask -> uint8 (auto-detect int32 vs uint8 serialization).
// ============================================================================
__global__ void mask_conv_kernel(const void* __restrict__ mask,
                                 unsigned char* __restrict__ m8)
{
    __shared__ int s_byte;
    if (threadIdx.x == 0) {
        const unsigned int* mi = (const unsigned int*)mask;
        int bm = 0;
#pragma unroll 8
        for (int i = 0; i < 64; i++) if (mi[i] > 1u) bm = 1;
        s_byte = bm;
    }
    __syncthreads();
    size_t i = (size_t)blockIdx.x * blockDim.x + threadIdx.x;
    uchar4 o;
    if (s_byte) {
        uchar4 v = ((const uchar4*)mask)[i];
        o.x = v.x != 0; o.y = v.y != 0; o.z = v.z != 0; o.w = v.w != 0;
    } else {
        int4 v = ((const int4*)mask)[i];
        o.x = v.x != 0; o.y = v.y != 0; o.z = v.z != 0; o.w = v.w != 0;
    }
    ((uchar4*)m8)[i] = o;
}

// ============================================================================
// Residual add + LayerNorm
// ============================================================================
__global__ void ln_kernel(const float* __restrict__ fc,
                          const float* __restrict__ resid,
                          const float* __restrict__ gamma,
                          const float* __restrict__ beta,
                          float* __restrict__ out)
{
    size_t base = (size_t)blockIdx.x * E_;
    int tid = threadIdx.x;
    float x0 = fc[base + tid] + resid[base + tid];
    float x1 = fc[base + tid + 256] + resid[base + tid + 256];
    float s = x0 + x1;
    float ss = x0 * x0 + x1 * x1;

    __shared__ float rs[8], rss[8];
#pragma unroll
    for (int o = 16; o; o >>= 1) {
        s  += __shfl_xor_sync(0xffffffffu, s, o);
        ss += __shfl_xor_sync(0xffffffffu, ss, o);
    }
    if ((tid & 31) == 0) { rs[tid >> 5] = s; rss[tid >> 5] = ss; }
    __syncthreads();
    s = 0.f; ss = 0.f;
#pragma unroll
    for (int i = 0; i < 8; i++) { s += rs[i]; ss += rss[i]; }

    float mu = s * (1.0f / E_);
    float var = ss * (1.0f / E_) - mu * mu;
    float rstd = rsqrtf(var + 1e-5f);
    out[base + tid]       = (x0 - mu) * rstd * gamma[tid] + beta[tid];
    out[base + tid + 256] = (x1 - mu) * rstd * gamma[tid + 256] + beta[tid + 256];
}

// ============================================================================
extern "C" void kernel_launch(void* const* d_in, const int* in_sizes, int n_in,
                              void* d_out, int out_size)
{
    const float* q    = (const float*)d_in[0];
    const float* k    = (const float*)d_in[1];
    const float* v    = (const float*)d_in[2];
    const void*  mask = (const void*)d_in[3];
    const float* Wq   = (const float*)d_in[4];
    const float* bq   = (const float*)d_in[5];
    const float* Wk   = (const float*)d_in[6];
    const float* bk   = (const float*)d_in[7];
    const float* Wv   = (const float*)d_in[8];
    const float* bv   = (const float*)d_in[9];
    const float* Wfc  = (const float*)d_in[10];
    const float* bfc  = (const float*)d_in[11];
    const float* gamma = (const float*)d_in[12];
    const float* beta  = (const float*)d_in[13];

    float* out  = (float*)d_out;
    float* attn = out + (size_t)B_ * L_ * E_;

    float *vh, *fc;
    bf16 *qhi, *qlo, *khi, *klo, *ihi, *ilo, *whi, *wlo;
    bf16 *ctxhi, *ctxlo, *vhiT, *vloT;
    unsigned char* m8;
    cudaGetSymbolAddress((void**)&vh,    g_vh);
    cudaGetSymbolAddress((void**)&fc,    g_fc);
    cudaGetSymbolAddress((void**)&qhi,   g_qhi);
    cudaGetSymbolAddress((void**)&qlo,   g_qlo);
    cudaGetSymbolAddress((void**)&khi,   g_khi);
    cudaGetSymbolAddress((void**)&klo,   g_klo);
    cudaGetSymbolAddress((void**)&ihi,   g_ihi);
    cudaGetSymbolAddress((void**)&ilo,   g_ilo);
    cudaGetSymbolAddress((void**)&whi,   g_whi);
    cudaGetSymbolAddress((void**)&wlo,   g_wlo);
    cudaGetSymbolAddress((void**)&ctxhi, g_ctxhi);
    cudaGetSymbolAddress((void**)&ctxlo, g_ctxlo);
    cudaGetSymbolAddress((void**)&vhiT,  g_vhiT);
    cudaGetSymbolAddress((void**)&vloT,  g_vloT);
    cudaGetSymbolAddress((void**)&m8,    g_mask8);

    cudaFuncSetAttribute(attn_fused_kernel,
                         cudaFuncAttributeMaxDynamicSharedMemorySize, AF_SMEM_BYTES);
    cudaFuncSetAttribute(qkv_hmma_kernel,
                         cudaFuncAttributeMaxDynamicSharedMemorySize, HMMA_SMEM);
    cudaFuncSetAttribute(fc_hmma_kernel,
                         cudaFuncAttributeMaxDynamicSharedMemorySize, HMMA_SMEM);

    // mask -> uint8
    mask_conv_kernel<<<(B_ * L_ * L_) / (4 * 256), 256>>>(mask, m8);

    // input + weight splits
    dim3 gsi((B_ * L_ * E_) / (4 * 256), 3);
    split_in_kernel<<<gsi, 256>>>(q, k, v, ihi, ilo);
    dim3 gsw((E_ * E_) / (4 * 256), 4);
    split_w_kernel<<<gsw, 256>>>(Wq, Wk, Wv, Wfc, whi, wlo);

    // QKV projections via HMMA
    dim3 gqkv(E_ / 128, (B_ * L_) / 128, 3);
    qkv_hmma_kernel<<<gqkv, 256, HMMA_SMEM>>>(ihi, ilo, whi, wlo, bq, bk, bv,
                                              qhi, qlo, khi, klo, vh);

    // V transpose + split
    dim3 gvt(H_ * B_, L_ / 64);
    vT_kernel<<<gvt, 256>>>(vh, vhiT, vloT);

    // fused attention: scores + softmax + AV + attn output
    dim3 gaf(L_ / 128, H_ * B_);              // (16, 32)
    attn_fused_kernel<<<gaf, 256, AF_SMEM_BYTES>>>(
        qhi, qlo, khi, klo, vhiT, vloT, m8, attn, ctxhi, ctxlo);

    // FC via HMMA
    dim3 gfc(E_ / 128, (B_ * L_) / 128);
    fc_hmma_kernel<<<gfc, 256, HMMA_SMEM>>>(ctxhi, ctxlo, whi, wlo, bfc, fc);

    // residual + LayerNorm
    ln_kernel<<<B_ * L_, 256>>>(fc, q, gamma, beta, out);
}